// round 9
// baseline (speedup 1.0000x reference)
#include <cuda_runtime.h>
#include <cuda_fp16.h>
#include <stdint.h>

#define D 768
#define H 64
#define E 7
#define BMAX 32768
#define NHB 64

// ---------------- device scratch ----------------
__device__ int d_offsets[E + 1];
__device__ int d_cursor[E];
__device__ int d_blk[NHB * E];
__device__ int d_perm[BMAX];
__device__ int d_is64;
__device__ int d_tick;
__device__ __align__(16) __half d_w1t[E * H * D];   // [e][n(H)][k(D)] fp16
__device__ __align__(16) __half d_w2t[E * D * H];   // [e][n(D)][k(H)] fp16

// ---------------- helpers ----------------
__device__ __forceinline__ uint32_t smem_u32(const void* p) {
    uint32_t a;
    asm("{ .reg .u64 t; cvta.to.shared.u64 t, %1; cvt.u32.u64 %0, t; }" : "=r"(a) : "l"(p));
    return a;
}
__device__ __forceinline__ uint32_t pack2(float a, float b) {
    __half2 h = __floats2half2_rn(a, b);
    return *(uint32_t*)&h;
}
__device__ __forceinline__ void cpa16(uint32_t dst, const void* src) {
    asm volatile("cp.async.cg.shared.global [%0], [%1], 16;" :: "r"(dst), "l"(src));
}
#define CP_COMMIT() asm volatile("cp.async.commit_group;" ::: "memory")
#define CP_WAIT0()  asm volatile("cp.async.wait_group 0;" ::: "memory")
#define LDM4(r0, r1, r2, r3, addr) \
    asm volatile("ldmatrix.sync.aligned.m8n8.x4.shared.b16 {%0,%1,%2,%3}, [%4];" \
        : "=r"(r0), "=r"(r1), "=r"(r2), "=r"(r3) : "r"(addr))

__device__ __forceinline__ void mma_f16(float* c, uint32_t a0, uint32_t a1, uint32_t a2,
                                        uint32_t a3, uint32_t b0, uint32_t b1) {
    asm volatile(
        "mma.sync.aligned.m16n8k16.row.col.f32.f16.f16.f32 "
        "{%0,%1,%2,%3}, {%4,%5,%6,%7}, {%8,%9}, {%0,%1,%2,%3};\n"
        : "+f"(c[0]), "+f"(c[1]), "+f"(c[2]), "+f"(c[3])
        : "r"(a0), "r"(a1), "r"(a2), "r"(a3), "r"(b0), "r"(b1));
}
__device__ __forceinline__ int load_id(const void* ids, int i, int is64) {
    return is64 ? (int)((const long long*)ids)[i] : ((const int*)ids)[i];
}

// ---------------- launch 1: histogram + last-block scan ----------------
__global__ void __launch_bounds__(256) k_histscan(const void* __restrict__ ids, int B) {
    __shared__ int sc[E];
    __shared__ int sbad;
    __shared__ int ticket;
    const int t = threadIdx.x;
    if (t < E) sc[t] = 0;
    if (t == 0) sbad = 0;
    __syncthreads();
    {   // dtype probe: int64 ids all in [0,E); int32 viewed as int64 fails w.p. ~1
        const long long* p = (const long long*)ids;
        int n = min(B / 2, 256);
        if (t < n) { long long v = p[t]; if (v < 0 || v >= E) sbad = 1; }
    }
    __syncthreads();
    const int is64 = !sbad;
    if (blockIdx.x == 0 && t == 0) d_is64 = is64;
    for (int i = blockIdx.x * 256 + t; i < B; i += NHB * 256) {
        int e = load_id(ids, i, is64);
        if ((unsigned)e < E) atomicAdd(&sc[e], 1);
    }
    __syncthreads();
    if (t < E) d_blk[blockIdx.x * E + t] = sc[t];
    __threadfence();
    if (t == 0) ticket = atomicAdd(&d_tick, 1);
    __syncthreads();
    if (ticket == NHB - 1 && t == 0) {
        int a = 0;
        for (int e = 0; e < E; e++) {
            int s = 0;
            for (int b = 0; b < NHB; b++) s += d_blk[b * E + e];
            d_offsets[e] = a; d_cursor[e] = a; a += s;
        }
        d_offsets[E] = a;
        d_tick = 0;
    }
}

// ---------------- launch 2: fused scatter + weight cvt/transpose ----------------
__global__ void __launch_bounds__(256) k_fuse(const void* __restrict__ ids, int B,
                                              const float* __restrict__ W1,
                                              const float* __restrict__ W2) {
    const int blk = blockIdx.x;
    if (blk < NHB) {
        const int is64 = d_is64;
        for (int i = blk * 256 + threadIdx.x; i < B; i += NHB * 256) {
            int e = load_id(ids, i, is64);
            if ((unsigned)e < E) {
                int p = atomicAdd(&d_cursor[e], 1);
                d_perm[p] = i;
            }
        }
    } else {
        const int nb = gridDim.x - NHB;
        const int n1 = E * D * H;
        for (int idx = (blk - NHB) * 256 + threadIdx.x; idx < 2 * n1; idx += nb * 256) {
            if (idx < n1) {   // W1: [e][k(D)][n(H)] -> w1t [e][n][k]
                int e = idx / (D * H);
                int rem = idx - e * D * H;
                int k = rem / H, n = rem - k * H;
                d_w1t[((size_t)e * H + n) * D + k] = __float2half(W1[idx]);
            } else {          // W2: [e][k(H)][n(D)] -> w2t [e][n][k]
                int j = idx - n1;
                int e = j / (H * D);
                int rem = j - e * H * D;
                int k = rem / D, n = rem - k * D;
                d_w2t[((size_t)e * D + n) * H + k] = __float2half(W2[j]);
            }
        }
    }
}

// ---------------- smem layout (bytes) ----------------
// union Xs[2]/W2[2] @ 0     : 2*9216 = 18432
// W1[2]             @ 18432 : 18432
// b1s f32           @ 36864 : 256
// b2s f32 (384)     @ 37120 : 1536
// rowI int          @ 38656 : 256
#define ROWB 144
#define SMEM_BYTES 38912

// ---------------- launch 3: main kernel (split-N CTAs, register-h) ----------------
__global__ void __launch_bounds__(128)
k_main(const float* __restrict__ x, const float* __restrict__ b1,
       const float* __restrict__ b2, float* __restrict__ out)
{
    const int e = blockIdx.y;
    const int rt = blockIdx.x >> 1;          // row tile
    const int nhf = blockIdx.x & 1;          // N half: cols [nhf*384, +384)
    const int seg0 = d_offsets[e], seg1 = d_offsets[e + 1];
    const int row0 = seg0 + rt * 64;
    if (row0 >= seg1) return;
    const int nrows = min(64, seg1 - row0);

    extern __shared__ char smc[];
    const uint32_t sb = smem_u32(smc);
    float* b1s = (float*)(smc + 36864);
    float* b2s = (float*)(smc + 37120);
    int*   rowI = (int*)(smc + 38656);

    const int tid = threadIdx.x, w = tid >> 5, lane = tid & 31;
    const int g = lane >> 2, tig = lane & 3;

    if (tid < 64) {
        rowI[tid] = d_perm[row0 + min(tid, nrows - 1)];
        b1s[tid] = b1[e * H + tid];
    }
    for (int i = tid; i < 384; i += 128) b2s[i] = b2[e * D + nhf * 384 + i];
    __syncthreads();

    const __half* W1e = d_w1t + (size_t)e * H * D;
    const __half* W2e = d_w2t + ((size_t)e * D + nhf * 384) * H;

    const int r = tid >> 1, s = tid & 1;
    const float* xg = x + (size_t)rowI[r] * D + s * 32;
    const __half* w1_src = W1e + r * D + s * 32;          // r = n-row of W1
    const __half* w2_src = W2e + r * H + s * 32;          // r = n-row of W2 chunk 0

    const uint32_t xw_dst = sb + r * ROWB + s * 64;       // + b*9216 (union)
    const uint32_t w1_dst = sb + 18432 + r * ROWB + s * 64;
    const uint32_t a_core = sb + (w * 16 + (lane & 15)) * ROWB + ((lane >> 4) & 1) * 16;
    const uint32_t b_core = ((lane & 7) + ((lane >> 4) & 1) * 8) * ROWB + ((lane >> 3) & 1) * 16;

    // ---- prologue: X0 + W1(0) ----
    float4 xr[8];
#pragma unroll
    for (int q = 0; q < 8; q++) xr[q] = __ldg((const float4*)xg + q);
#pragma unroll
    for (int q = 0; q < 4; q++) cpa16(w1_dst + q * 16, w1_src + q * 8);
    CP_COMMIT();
    {
        uint32_t* xd = (uint32_t*)(smc + r * ROWB + s * 64);
#pragma unroll
        for (int q = 0; q < 8; q++) {
            xd[2 * q]     = pack2(xr[q].x, xr[q].y);
            xd[2 * q + 1] = pack2(xr[q].z, xr[q].w);
        }
    }
    CP_WAIT0();
    __syncthreads();

    // ============ GEMM1: h = relu(X @ W1^T + b1), 12 K-chunks of 64 ============
    float acc[8][4];
#pragma unroll
    for (int nt = 0; nt < 8; nt++)
#pragma unroll
        for (int q = 0; q < 4; q++) acc[nt][q] = 0.f;

#pragma unroll 1
    for (int i = 0; i < 12; i++) {
        const int b = i & 1;
        if (i < 11) {
            const __half* ws = w1_src + (i + 1) * 64;
            const uint32_t wd = w1_dst + (b ^ 1) * 9216;
#pragma unroll
            for (int q = 0; q < 4; q++) cpa16(wd + q * 16, ws + q * 8);
            CP_COMMIT();
            const float4* xsrc = (const float4*)(xg + (i + 1) * 64);
#pragma unroll
            for (int q = 0; q < 8; q++) xr[q] = __ldg(xsrc + q);
        }
        const uint32_t aB = a_core + b * 9216;
        const uint32_t wB = sb + 18432 + b * 9216 + b_core;
#pragma unroll
        for (int ks = 0; ks < 4; ks++) {
            uint32_t a0, a1, a2, a3;
            LDM4(a0, a1, a2, a3, aB + ks * 32);
#pragma unroll
            for (int jt = 0; jt < 4; jt++) {
                uint32_t r0, r1, r2, r3;
                LDM4(r0, r1, r2, r3, wB + jt * 16 * ROWB + ks * 32);
                mma_f16(acc[2 * jt],     a0, a1, a2, a3, r0, r1);
                mma_f16(acc[2 * jt + 1], a0, a1, a2, a3, r2, r3);
            }
        }
        if (i < 11) {
            uint32_t* xd = (uint32_t*)(smc + (b ^ 1) * 9216 + r * ROWB + s * 64);
#pragma unroll
            for (int q = 0; q < 8; q++) {
                xd[2 * q]     = pack2(xr[q].x, xr[q].y);
                xd[2 * q + 1] = pack2(xr[q].z, xr[q].w);
            }
        }
        CP_WAIT0();
        __syncthreads();
    }

    // ---- prefetch W2(0) into union buf0 (X released) ----
#pragma unroll
    for (int q = 0; q < 4; q++) cpa16(xw_dst + q * 16, w2_src + q * 8);
    CP_COMMIT();

    // ---- register transform: GEMM1 D-frags -> GEMM2 A-frags (bias+relu+fp16) ----
    // A(m16k16, block ks): a0=(row g, k=16ks+2tig..), a1=(row g+8, same), a2=(row g, +8), a3=(row g+8, +8)
    // D cols nt*8+2tig: nt=2ks gives k=16ks+2tig; nt=2ks+1 gives 16ks+8+2tig.
    uint32_t ha[4][4];
#pragma unroll
    for (int ks = 0; ks < 4; ks++) {
        const int c0 = (2 * ks) * 8 + 2 * tig;
        const int c1 = c0 + 8;
        float f0 = acc[2 * ks][0] + b1s[c0];
        float f1 = acc[2 * ks][1] + b1s[c0 + 1];
        float f2 = acc[2 * ks][2] + b1s[c0];
        float f3 = acc[2 * ks][3] + b1s[c0 + 1];
        float f4 = acc[2 * ks + 1][0] + b1s[c1];
        float f5 = acc[2 * ks + 1][1] + b1s[c1 + 1];
        float f6 = acc[2 * ks + 1][2] + b1s[c1];
        float f7 = acc[2 * ks + 1][3] + b1s[c1 + 1];
        ha[ks][0] = pack2(f0 > 0.f ? f0 : 0.f, f1 > 0.f ? f1 : 0.f);
        ha[ks][1] = pack2(f2 > 0.f ? f2 : 0.f, f3 > 0.f ? f3 : 0.f);
        ha[ks][2] = pack2(f4 > 0.f ? f4 : 0.f, f5 > 0.f ? f5 : 0.f);
        ha[ks][3] = pack2(f6 > 0.f ? f6 : 0.f, f7 > 0.f ? f7 : 0.f);
    }
    CP_WAIT0();
    __syncthreads();

    // per-thread row contexts for epilogue2 (pointers pre-offset to this CTA's N-half)
    const int rlo = w * 16 + g, rhi = rlo + 8;
    const bool vlo = rlo < nrows, vhi = rhi < nrows;
    const float* xlo = x + (size_t)rowI[rlo] * D + nhf * 384;
    const float* xhi = x + (size_t)rowI[rhi] * D + nhf * 384;
    float* olo = out + (size_t)rowI[rlo] * D + nhf * 384;
    float* ohi = out + (size_t)rowI[rhi] * D + nhf * 384;

    // ============ GEMM2: out = x + h @ W2^T + b2, 6 N-chunks of 64 ============
#pragma unroll 1
    for (int j = 0; j < 6; j++) {
        const int b = j & 1;
        if (j < 5) {
            const __half* ws = w2_src + (size_t)(j + 1) * 64 * H;
            const uint32_t wd = xw_dst + (b ^ 1) * 9216;
#pragma unroll
            for (int q = 0; q < 4; q++) cpa16(wd + q * 16, ws + q * 8);
            CP_COMMIT();
        }
        float acc2[8][4];
#pragma unroll
        for (int nt = 0; nt < 8; nt++)
#pragma unroll
            for (int q = 0; q < 4; q++) acc2[nt][q] = 0.f;

        const uint32_t wB = sb + b * 9216 + b_core;
#pragma unroll
        for (int ks = 0; ks < 4; ks++) {
#pragma unroll
            for (int jt = 0; jt < 4; jt++) {
                uint32_t r0, r1, r2, r3;
                LDM4(r0, r1, r2, r3, wB + jt * 16 * ROWB + ks * 32);
                mma_f16(acc2[2 * jt],     ha[ks][0], ha[ks][1], ha[ks][2], ha[ks][3], r0, r1);
                mma_f16(acc2[2 * jt + 1], ha[ks][0], ha[ks][1], ha[ks][2], ha[ks][3], r2, r3);
            }
        }

        // fused epilogue (overlaps next W2 cp.async)
#pragma unroll
        for (int nt = 0; nt < 8; nt++) {
            const int cl = j * 64 + nt * 8 + 2 * tig;
            float2 bv = *(const float2*)(b2s + cl);
            if (vlo) {
                float2 xv = *(const float2*)(xlo + cl);
                float2 o = make_float2(xv.x + acc2[nt][0] + bv.x,
                                       xv.y + acc2[nt][1] + bv.y);
                *(float2*)(olo + cl) = o;
            }
            if (vhi) {
                float2 xv = *(const float2*)(xhi + cl);
                float2 o = make_float2(xv.x + acc2[nt][2] + bv.x,
                                       xv.y + acc2[nt][3] + bv.y);
                *(float2*)(ohi + cl) = o;
            }
        }
        CP_WAIT0();
        __syncthreads();
    }
}

extern "C" void kernel_launch(void* const* d_in, const int* in_sizes, int n_in,
                              void* d_out, int out_size)
{
    const float* x   = (const float*)d_in[0];
    const void*  ids = d_in[1];
    const float* W1  = (const float*)d_in[2];
    const float* b1  = (const float*)d_in[3];
    const float* W2  = (const float*)d_in[4];
    const float* b2  = (const float*)d_in[5];
    float*       out = (float*)d_out;

    const int B = in_sizes[1];

    k_histscan<<<NHB, 256>>>(ids, B);
    k_fuse<<<NHB + 84, 256>>>(ids, B, W1, W2);

    cudaFuncSetAttribute(k_main, cudaFuncAttributeMaxDynamicSharedMemorySize, SMEM_BYTES);
    dim3 grid(((B + 63) / 64) * 2, E);
    k_main<<<grid, 128, SMEM_BYTES>>>(x, b1, b2, out);
}

// round 10
// speedup vs baseline: 1.3085x; 1.3085x over previous
#include <cuda_runtime.h>
#include <cuda_fp16.h>
#include <stdint.h>

#define D 768
#define H 64
#define E 7
#define BMAX 32768
#define NHB 64

// ---------------- device scratch ----------------
__device__ int d_offsets[E + 1];
__device__ int d_cursor[E];
__device__ int d_blk[NHB * E];
__device__ int d_perm[BMAX];
__device__ int d_is64;
__device__ int d_tick;
__device__ __align__(16) __half d_w1t[E * H * D];   // [e][n(H)][k(D)] fp16
__device__ __align__(16) __half d_w2t[E * D * H];   // [e][n(D)][k(H)] fp16

// ---------------- helpers ----------------
__device__ __forceinline__ uint32_t smem_u32(const void* p) {
    uint32_t a;
    asm("{ .reg .u64 t; cvta.to.shared.u64 t, %1; cvt.u32.u64 %0, t; }" : "=r"(a) : "l"(p));
    return a;
}
__device__ __forceinline__ uint32_t pack2(float a, float b) {
    __half2 h = __floats2half2_rn(a, b);
    return *(uint32_t*)&h;
}
__device__ __forceinline__ void cpa16(uint32_t dst, const void* src) {
    asm volatile("cp.async.cg.shared.global [%0], [%1], 16;" :: "r"(dst), "l"(src));
}
#define CP_COMMIT() asm volatile("cp.async.commit_group;" ::: "memory")
#define CP_WAIT0()  asm volatile("cp.async.wait_group 0;" ::: "memory")
#define LDM4(r0, r1, r2, r3, addr) \
    asm volatile("ldmatrix.sync.aligned.m8n8.x4.shared.b16 {%0,%1,%2,%3}, [%4];" \
        : "=r"(r0), "=r"(r1), "=r"(r2), "=r"(r3) : "r"(addr))

__device__ __forceinline__ void mma_f16(float* c, uint32_t a0, uint32_t a1, uint32_t a2,
                                        uint32_t a3, uint32_t b0, uint32_t b1) {
    asm volatile(
        "mma.sync.aligned.m16n8k16.row.col.f32.f16.f16.f32 "
        "{%0,%1,%2,%3}, {%4,%5,%6,%7}, {%8,%9}, {%0,%1,%2,%3};\n"
        : "+f"(c[0]), "+f"(c[1]), "+f"(c[2]), "+f"(c[3])
        : "r"(a0), "r"(a1), "r"(a2), "r"(a3), "r"(b0), "r"(b1));
}
__device__ __forceinline__ int load_id(const void* ids, int i, int is64) {
    return is64 ? (int)((const long long*)ids)[i] : ((const int*)ids)[i];
}

// ---------------- launch 1: histogram + last-block scan ----------------
__global__ void __launch_bounds__(256) k_histscan(const void* __restrict__ ids, int B) {
    __shared__ int sc[E];
    __shared__ int sbad;
    __shared__ int ticket;
    const int t = threadIdx.x;
    if (t < E) sc[t] = 0;
    if (t == 0) sbad = 0;
    __syncthreads();
    {   // dtype probe: int64 ids all in [0,E); int32 viewed as int64 fails w.p. ~1
        const long long* p = (const long long*)ids;
        int n = min(B / 2, 256);
        if (t < n) { long long v = p[t]; if (v < 0 || v >= E) sbad = 1; }
    }
    __syncthreads();
    const int is64 = !sbad;
    if (blockIdx.x == 0 && t == 0) d_is64 = is64;
    for (int i = blockIdx.x * 256 + t; i < B; i += NHB * 256) {
        int e = load_id(ids, i, is64);
        if ((unsigned)e < E) atomicAdd(&sc[e], 1);
    }
    __syncthreads();
    if (t < E) d_blk[blockIdx.x * E + t] = sc[t];
    __threadfence();
    if (t == 0) ticket = atomicAdd(&d_tick, 1);
    __syncthreads();
    if (ticket == NHB - 1 && t == 0) {
        int a = 0;
        for (int e = 0; e < E; e++) {
            int s = 0;
            for (int b = 0; b < NHB; b++) s += d_blk[b * E + e];
            d_offsets[e] = a; d_cursor[e] = a; a += s;
        }
        d_offsets[E] = a;
        d_tick = 0;
    }
}

// ---------------- launch 2: fused scatter + weight cvt/transpose ----------------
__global__ void __launch_bounds__(256) k_fuse(const void* __restrict__ ids, int B,
                                              const float* __restrict__ W1,
                                              const float* __restrict__ W2) {
    const int blk = blockIdx.x;
    if (blk < NHB) {
        const int is64 = d_is64;
        for (int i = blk * 256 + threadIdx.x; i < B; i += NHB * 256) {
            int e = load_id(ids, i, is64);
            if ((unsigned)e < E) {
                int p = atomicAdd(&d_cursor[e], 1);
                d_perm[p] = i;
            }
        }
    } else {
        const int nb = gridDim.x - NHB;
        const int n1 = E * D * H;
        for (int idx = (blk - NHB) * 256 + threadIdx.x; idx < 2 * n1; idx += nb * 256) {
            if (idx < n1) {   // W1: [e][k(D)][n(H)] -> w1t [e][n][k]
                int e = idx / (D * H);
                int rem = idx - e * D * H;
                int k = rem / H, n = rem - k * H;
                d_w1t[((size_t)e * H + n) * D + k] = __float2half(W1[idx]);
            } else {          // W2: [e][k(H)][n(D)] -> w2t [e][n][k]
                int j = idx - n1;
                int e = j / (H * D);
                int rem = j - e * H * D;
                int k = rem / D, n = rem - k * D;
                d_w2t[((size_t)e * D + n) * H + k] = __float2half(W2[j]);
            }
        }
    }
}

// ---------------- smem layout (bytes) ----------------
// Hs          @ 0     : 64 rows * 144B = 9216
// Xs[2]/W2[2] @ 9216  : 2*9216 = 18432  (union)
// W1[2]       @ 27648 : 18432
// b1s f32     @ 46080 : 256
// b2s f32     @ 46336 : 3072
// rowI int    @ 49408 : 256
#define ROWB 144
#define SMEM_BYTES 49664

// ---------------- launch 3: main kernel (8 warps: 4 M-warps x 2 N-warps) ----------------
__global__ void __launch_bounds__(256, 3)
k_main(const float* __restrict__ x, const float* __restrict__ b1,
       const float* __restrict__ b2, float* __restrict__ out)
{
    const int e = blockIdx.y;
    const int seg0 = d_offsets[e], seg1 = d_offsets[e + 1];
    const int row0 = seg0 + blockIdx.x * 64;
    if (row0 >= seg1) return;
    const int nrows = min(64, seg1 - row0);

    extern __shared__ char smc[];
    const uint32_t sb = smem_u32(smc);
    float* b1s = (float*)(smc + 46080);
    float* b2s = (float*)(smc + 46336);
    int*   rowI = (int*)(smc + 49408);

    const int tid = threadIdx.x, w = tid >> 5, lane = tid & 31;
    const int mw = w & 3, nw = w >> 2;          // M-warp group, N-warp half
    const int g = lane >> 2, tig = lane & 3;

    if (tid < 64) {
        rowI[tid] = d_perm[row0 + min(tid, nrows - 1)];
        b1s[tid] = b1[e * H + tid];
    }
    for (int i = tid; i < D; i += 256) b2s[i] = b2[e * D + i];
    __syncthreads();

    const __half* W1e = d_w1t + (size_t)e * H * D;
    const __half* W2e = d_w2t + (size_t)e * D * H;

    // loaders: r = row / n-row (0..63), s = 16-element segment (0..3)
    const int r = tid >> 2, s = tid & 3;
    const float* xg = x + (size_t)rowI[r] * D + s * 16;
    const __half* w1_src = W1e + r * D + s * 16;
    const __half* w2_src = W2e + r * H + s * 16;

    const uint32_t x_dst  = sb + 9216 + r * ROWB + s * 32;    // + b*9216
    const uint32_t w1_dst = sb + 27648 + r * ROWB + s * 32;   // + b*9216
    const uint32_t w2_dst = sb + 9216 + r * ROWB + s * 32;    // + b*9216

    // fragment address cores
    const uint32_t a_core = sb + 9216 + (mw * 16 + (lane & 15)) * ROWB + ((lane >> 4) & 1) * 16;
    const uint32_t h_core = sb + (mw * 16 + (lane & 15)) * ROWB + ((lane >> 4) & 1) * 16;
    const uint32_t b_core = (nw * 32 + (lane & 7) + ((lane >> 4) & 1) * 8) * ROWB
                          + ((lane >> 3) & 1) * 16;

    // ---- prologue: X0 (LDG+cvt+STS) + W1(0) (cp.async) ----
    float4 xr[4];
#pragma unroll
    for (int q = 0; q < 4; q++) xr[q] = __ldg((const float4*)xg + q);
#pragma unroll
    for (int q = 0; q < 2; q++) cpa16(w1_dst + q * 16, w1_src + q * 8);
    CP_COMMIT();
    {
        uint32_t* xd = (uint32_t*)(smc + 9216 + r * ROWB + s * 32);
#pragma unroll
        for (int q = 0; q < 4; q++) {
            xd[2 * q]     = pack2(xr[q].x, xr[q].y);
            xd[2 * q + 1] = pack2(xr[q].z, xr[q].w);
        }
    }
    CP_WAIT0();
    __syncthreads();

    // ============ GEMM1: h = relu(X @ W1^T + b1), 12 K-chunks of 64 ============
    float acc[4][4];
#pragma unroll
    for (int nt = 0; nt < 4; nt++)
#pragma unroll
        for (int q = 0; q < 4; q++) acc[nt][q] = 0.f;

#pragma unroll 1
    for (int i = 0; i < 12; i++) {
        const int b = i & 1;
        if (i < 11) {
            const __half* ws = w1_src + (i + 1) * 64;
            const uint32_t wd = w1_dst + (b ^ 1) * 9216;
#pragma unroll
            for (int q = 0; q < 2; q++) cpa16(wd + q * 16, ws + q * 8);
            CP_COMMIT();
            const float4* xsrc = (const float4*)(xg + (i + 1) * 64);
#pragma unroll
            for (int q = 0; q < 4; q++) xr[q] = __ldg(xsrc + q);
        }
        const uint32_t aB = a_core + b * 9216;
        const uint32_t wB = sb + 27648 + b * 9216 + b_core;
#pragma unroll
        for (int ks = 0; ks < 4; ks++) {
            uint32_t a0, a1, a2, a3;
            LDM4(a0, a1, a2, a3, aB + ks * 32);
#pragma unroll
            for (int jt = 0; jt < 2; jt++) {
                uint32_t r0, r1, r2, r3;
                LDM4(r0, r1, r2, r3, wB + jt * 16 * ROWB + ks * 32);
                mma_f16(acc[2 * jt],     a0, a1, a2, a3, r0, r1);
                mma_f16(acc[2 * jt + 1], a0, a1, a2, a3, r2, r3);
            }
        }
        if (i < 11) {
            uint32_t* xd = (uint32_t*)(smc + 9216 + (b ^ 1) * 9216 + r * ROWB + s * 32);
#pragma unroll
            for (int q = 0; q < 4; q++) {
                xd[2 * q]     = pack2(xr[q].x, xr[q].y);
                xd[2 * q + 1] = pack2(xr[q].z, xr[q].w);
            }
        }
        CP_WAIT0();
        __syncthreads();
    }

    // ---- epilogue1: Hs = fp16(relu(acc + b1)) (warp writes its 16r x 32c patch) ----
#pragma unroll
    for (int nt = 0; nt < 4; nt++) {
        const int c = nw * 32 + nt * 8 + 2 * tig;
        float v0 = acc[nt][0] + b1s[c];
        float v1 = acc[nt][1] + b1s[c + 1];
        float v2 = acc[nt][2] + b1s[c];
        float v3 = acc[nt][3] + b1s[c + 1];
        *(uint32_t*)(smc + (mw * 16 + g) * ROWB + c * 2) =
            pack2(v0 > 0.f ? v0 : 0.f, v1 > 0.f ? v1 : 0.f);
        *(uint32_t*)(smc + (mw * 16 + g + 8) * ROWB + c * 2) =
            pack2(v2 > 0.f ? v2 : 0.f, v3 > 0.f ? v3 : 0.f);
    }

    // ---- prefetch W2(0) into union buf0 (X released by last GEMM1 sync) ----
#pragma unroll
    for (int q = 0; q < 2; q++) cpa16(w2_dst + q * 16, w2_src + q * 8);
    CP_COMMIT();
    __syncthreads();   // Hs visible to all warps

    // ---- A-fragments of h: loaded once for all 12 N-chunks ----
    uint32_t ha[4][4];
#pragma unroll
    for (int ks = 0; ks < 4; ks++)
        LDM4(ha[ks][0], ha[ks][1], ha[ks][2], ha[ks][3], h_core + ks * 32);
    CP_WAIT0();
    __syncthreads();

    // per-thread row contexts for epilogue2
    const int rlo = mw * 16 + g, rhi = rlo + 8;
    const bool vlo = rlo < nrows, vhi = rhi < nrows;
    const float* xlo = x + (size_t)rowI[rlo] * D;
    const float* xhi = x + (size_t)rowI[rhi] * D;
    float* olo = out + (size_t)rowI[rlo] * D;
    float* ohi = out + (size_t)rowI[rhi] * D;

    // ============ GEMM2: out = x + h @ W2^T + b2, 12 N-chunks of 64 ============
#pragma unroll 1
    for (int j = 0; j < 12; j++) {
        const int b = j & 1;
        if (j < 11) {
            const __half* ws = w2_src + (size_t)(j + 1) * 64 * H;
            const uint32_t wd = w2_dst + (b ^ 1) * 9216;
#pragma unroll
            for (int q = 0; q < 2; q++) cpa16(wd + q * 16, ws + q * 8);
            CP_COMMIT();
        }
        float acc2[4][4];
#pragma unroll
        for (int nt = 0; nt < 4; nt++)
#pragma unroll
            for (int q = 0; q < 4; q++) acc2[nt][q] = 0.f;

        const uint32_t wB = sb + 9216 + b * 9216 + b_core;
#pragma unroll
        for (int ks = 0; ks < 4; ks++) {
#pragma unroll
            for (int jt = 0; jt < 2; jt++) {
                uint32_t r0, r1, r2, r3;
                LDM4(r0, r1, r2, r3, wB + jt * 16 * ROWB + ks * 32);
                mma_f16(acc2[2 * jt],     ha[ks][0], ha[ks][1], ha[ks][2], ha[ks][3], r0, r1);
                mma_f16(acc2[2 * jt + 1], ha[ks][0], ha[ks][1], ha[ks][2], ha[ks][3], r2, r3);
            }
        }

        // fused epilogue: out = x + y + b2 (overlaps next W2 cp.async)
#pragma unroll
        for (int nt = 0; nt < 4; nt++) {
            const int cl = j * 64 + nw * 32 + nt * 8 + 2 * tig;
            float2 bv = *(const float2*)(b2s + cl);
            if (vlo) {
                float2 xv = *(const float2*)(xlo + cl);
                float2 o = make_float2(xv.x + acc2[nt][0] + bv.x,
                                       xv.y + acc2[nt][1] + bv.y);
                *(float2*)(olo + cl) = o;
            }
            if (vhi) {
                float2 xv = *(const float2*)(xhi + cl);
                float2 o = make_float2(xv.x + acc2[nt][2] + bv.x,
                                       xv.y + acc2[nt][3] + bv.y);
                *(float2*)(ohi + cl) = o;
            }
        }
        CP_WAIT0();
        __syncthreads();
    }
}

extern "C" void kernel_launch(void* const* d_in, const int* in_sizes, int n_in,
                              void* d_out, int out_size)
{
    const float* x   = (const float*)d_in[0];
    const void*  ids = d_in[1];
    const float* W1  = (const float*)d_in[2];
    const float* b1  = (const float*)d_in[3];
    const float* W2  = (const float*)d_in[4];
    const float* b2  = (const float*)d_in[5];
    float*       out = (float*)d_out;

    const int B = in_sizes[1];

    k_histscan<<<NHB, 256>>>(ids, B);
    k_fuse<<<NHB + 84, 256>>>(ids, B, W1, W2);

    cudaFuncSetAttribute(k_main, cudaFuncAttributeMaxDynamicSharedMemorySize, SMEM_BYTES);
    dim3 grid((B + 63) / 64, E);
    k_main<<<grid, 256, SMEM_BYTES>>>(x, b1, b2, out);
}

// round 12
// speedup vs baseline: 1.6410x; 1.2541x over previous
#include <cuda_runtime.h>
#include <cuda_fp16.h>
#include <stdint.h>

#define D 768
#define H 64
#define E 7
#define BMAX 32768
#define NHB 64

// ---------------- device scratch ----------------
__device__ int d_offsets[E + 1];
__device__ int d_cursor[E];
__device__ int d_blk[NHB * E];
__device__ int d_perm[BMAX];
__device__ int d_is64;
__device__ int d_tick;
__device__ __align__(16) __half d_w1t[E * H * D];   // [e][n(H)][k(D)] fp16
__device__ __align__(16) __half d_w2t[E * D * H];   // [e][n(D)][k(H)] fp16

// ---------------- helpers ----------------
__device__ __forceinline__ uint32_t smem_u32(const void* p) {
    uint32_t a;
    asm("{ .reg .u64 t; cvta.to.shared.u64 t, %1; cvt.u32.u64 %0, t; }" : "=r"(a) : "l"(p));
    return a;
}
__device__ __forceinline__ uint32_t pack2(float a, float b) {
    __half2 h = __floats2half2_rn(a, b);
    return *(uint32_t*)&h;
}
__device__ __forceinline__ void cpa16(uint32_t dst, const void* src) {
    asm volatile("cp.async.cg.shared.global [%0], [%1], 16;" :: "r"(dst), "l"(src));
}
#define CP_COMMIT() asm volatile("cp.async.commit_group;" ::: "memory")
#define CP_WAIT1()  asm volatile("cp.async.wait_group 1;" ::: "memory")
#define CP_WAIT0()  asm volatile("cp.async.wait_group 0;" ::: "memory")
#define LDM4(r0, r1, r2, r3, addr) \
    asm volatile("ldmatrix.sync.aligned.m8n8.x4.shared.b16 {%0,%1,%2,%3}, [%4];" \
        : "=r"(r0), "=r"(r1), "=r"(r2), "=r"(r3) : "r"(addr))

__device__ __forceinline__ void mma_f16(float* c, uint32_t a0, uint32_t a1, uint32_t a2,
                                        uint32_t a3, uint32_t b0, uint32_t b1) {
    asm volatile(
        "mma.sync.aligned.m16n8k16.row.col.f32.f16.f16.f32 "
        "{%0,%1,%2,%3}, {%4,%5,%6,%7}, {%8,%9}, {%0,%1,%2,%3};\n"
        : "+f"(c[0]), "+f"(c[1]), "+f"(c[2]), "+f"(c[3])
        : "r"(a0), "r"(a1), "r"(a2), "r"(a3), "r"(b0), "r"(b1));
}
__device__ __forceinline__ int load_id(const void* ids, int i, int is64) {
    return is64 ? (int)((const long long*)ids)[i] : ((const int*)ids)[i];
}

// ---------------- launch 1: histogram + last-block scan ----------------
__global__ void __launch_bounds__(256) k_histscan(const void* __restrict__ ids, int B) {
    __shared__ int sc[E];
    __shared__ int sbad;
    __shared__ int ticket;
    const int t = threadIdx.x;
    if (t < E) sc[t] = 0;
    if (t == 0) sbad = 0;
    __syncthreads();
    {   // dtype probe: int64 ids all in [0,E); int32 viewed as int64 fails w.p. ~1
        const long long* p = (const long long*)ids;
        int n = min(B / 2, 256);
        if (t < n) { long long v = p[t]; if (v < 0 || v >= E) sbad = 1; }
    }
    __syncthreads();
    const int is64 = !sbad;
    if (blockIdx.x == 0 && t == 0) d_is64 = is64;
    for (int i = blockIdx.x * 256 + t; i < B; i += NHB * 256) {
        int e = load_id(ids, i, is64);
        if ((unsigned)e < E) atomicAdd(&sc[e], 1);
    }
    __syncthreads();
    if (t < E) d_blk[blockIdx.x * E + t] = sc[t];
    __threadfence();
    if (t == 0) ticket = atomicAdd(&d_tick, 1);
    __syncthreads();
    if (ticket == NHB - 1 && t == 0) {
        int a = 0;
        for (int e = 0; e < E; e++) {
            int s = 0;
            for (int b = 0; b < NHB; b++) s += d_blk[b * E + e];
            d_offsets[e] = a; d_cursor[e] = a; a += s;
        }
        d_offsets[E] = a;
        d_tick = 0;
    }
}

// ---------------- launch 2: scatter + tiled weight cvt/transpose ----------------
// W1 tiles: 7*(24 k-tiles * 2 n-tiles) = 336; W2: 7*(2*24) = 336 -> 672 total.
__global__ void __launch_bounds__(256) k_fuse(const void* __restrict__ ids, int B,
                                              const float* __restrict__ W1,
                                              const float* __restrict__ W2) {
    const int blk = blockIdx.x;
    const int tid = threadIdx.x;
    if (blk < NHB) {
        const int is64 = d_is64;
        for (int i = blk * 256 + tid; i < B; i += NHB * 256) {
            int e = load_id(ids, i, is64);
            if ((unsigned)e < E) {
                int p = atomicAdd(&d_cursor[e], 1);
                d_perm[p] = i;
            }
        }
    } else {
        __shared__ float ts[32][33];
        const int nb = gridDim.x - NHB;
        const int tx = tid & 31, ty = tid >> 5;   // 8 rows per pass
        for (int tile = blk - NHB; tile < 672; tile += nb) {
            const float* src;
            __half* dst;
            int k0, n0, srcLD, dstLD;
            if (tile < 336) {           // W1 [D][H] -> w1t [H][D]
                int e = tile / 48, r = tile % 48;
                k0 = (r >> 1) * 32; n0 = (r & 1) * 32;
                src = W1 + (size_t)e * D * H;  srcLD = H;
                dst = d_w1t + (size_t)e * H * D; dstLD = D;
            } else {                    // W2 [H][D] -> w2t [D][H]
                int t2 = tile - 336;
                int e = t2 / 48, r = t2 % 48;
                k0 = (r / 24) * 32; n0 = (r % 24) * 32;
                src = W2 + (size_t)e * H * D;  srcLD = D;
                dst = d_w2t + (size_t)e * D * H; dstLD = H;
            }
#pragma unroll
            for (int p = 0; p < 4; p++)
                ts[ty + 8 * p][tx] = src[(size_t)(k0 + ty + 8 * p) * srcLD + n0 + tx];
            __syncthreads();
#pragma unroll
            for (int p = 0; p < 4; p++)
                dst[(size_t)(n0 + ty + 8 * p) * dstLD + k0 + tx] =
                    __float2half(ts[tx][ty + 8 * p]);
            __syncthreads();
        }
    }
}

// ---------------- smem layout (bytes) ----------------
// Hs        @ 0     : 9216
// Xs[2]     @ 9216  : 18432
// Wring[3]  @ 27648 : 27648
// b1s f32   @ 55296 : 256
// b2s f32   @ 55552 : 3072
// rowI int  @ 58624 : 256
#define ROWB 144
#define OFF_XS 9216
#define OFF_WR 27648
#define SMEM_BYTES 58880

// ---------------- launch 3: main kernel (8 warps, 3-stage W ring) ----------------
__global__ void __launch_bounds__(256)
k_main(const float* __restrict__ x, const float* __restrict__ b1,
       const float* __restrict__ b2, float* __restrict__ out)
{
    const int e = blockIdx.y;
    const int seg0 = d_offsets[e], seg1 = d_offsets[e + 1];
    const int row0 = seg0 + blockIdx.x * 64;
    if (row0 >= seg1) return;
    const int nrows = min(64, seg1 - row0);

    extern __shared__ char smc[];
    const uint32_t sb = smem_u32(smc);
    float* b1s = (float*)(smc + 55296);
    float* b2s = (float*)(smc + 55552);
    int*   rowI = (int*)(smc + 58624);

    const int tid = threadIdx.x, w = tid >> 5, lane = tid & 31;
    const int mw = w & 3, nw = w >> 2;
    const int g = lane >> 2, tig = lane & 3;

    if (tid < 64) {
        rowI[tid] = d_perm[row0 + min(tid, nrows - 1)];
        b1s[tid] = b1[e * H + tid];
    }
    for (int i = tid; i < D; i += 256) b2s[i] = b2[e * D + i];
    __syncthreads();

    const __half* W1e = d_w1t + (size_t)e * H * D;
    const __half* W2e = d_w2t + (size_t)e * D * H;

    // loaders: r = n-row (0..63), s = 16-element segment (0..3)
    const int r = tid >> 2, s = tid & 3;
    const float* xg = x + (size_t)rowI[r] * D + s * 16;
    const __half* w1_src = W1e + r * D + s * 16;
    const __half* w2_src = W2e + r * H + s * 16;
    const uint32_t wr_dst = sb + OFF_WR + r * ROWB + s * 32;   // + ring*9216

    // fragment address cores
    const uint32_t a_core = sb + OFF_XS + (mw * 16 + (lane & 15)) * ROWB + ((lane >> 4) & 1) * 16;
    const uint32_t h_core = sb + (mw * 16 + (lane & 15)) * ROWB + ((lane >> 4) & 1) * 16;
    const uint32_t b_core = (nw * 32 + (lane & 7) + ((lane >> 4) & 1) * 8) * ROWB
                          + ((lane >> 3) & 1) * 16;

    // ---- prologue: X0 LDG, W1 chunks 0,1 via ring slots 0,1 ----
    float4 xr[4];
#pragma unroll
    for (int q = 0; q < 4; q++) xr[q] = __ldg((const float4*)xg + q);
    {
        cpa16(wr_dst + 0,  w1_src + 0);
        cpa16(wr_dst + 16, w1_src + 8);
        CP_COMMIT();                                   // g0 = W1 chunk 0
        cpa16(wr_dst + 9216 + 0,  w1_src + 64 + 0);
        cpa16(wr_dst + 9216 + 16, w1_src + 64 + 8);
        CP_COMMIT();                                   // g1 = W1 chunk 1
    }
    {
        uint32_t* xd = (uint32_t*)(smc + OFF_XS + r * ROWB + s * 32);
#pragma unroll
        for (int q = 0; q < 4; q++) {
            xd[2 * q]     = pack2(xr[q].x, xr[q].y);
            xd[2 * q + 1] = pack2(xr[q].z, xr[q].w);
        }
    }
    CP_WAIT1();
    __syncthreads();

    // ============ GEMM1: h = relu(X @ W1^T + b1), 12 K-chunks of 64 ============
    float acc[4][4];
#pragma unroll
    for (int nt = 0; nt < 4; nt++)
#pragma unroll
        for (int q = 0; q < 4; q++) acc[nt][q] = 0.f;

    int rc = 2;  // ring slot for chunk i+2
#pragma unroll 1
    for (int i = 0; i < 12; i++) {
        if (i + 2 < 12) {
            const __half* ws = w1_src + (i + 2) * 64;
            const uint32_t wd = wr_dst + rc * 9216;
            cpa16(wd + 0, ws + 0);
            cpa16(wd + 16, ws + 8);
            CP_COMMIT();
            rc = (rc == 2) ? 0 : rc + 1;
        }
        if (i + 1 < 12) {
            const float4* xsrc = (const float4*)(xg + (i + 1) * 64);
#pragma unroll
            for (int q = 0; q < 4; q++) xr[q] = __ldg(xsrc + q);
        }
        const int b = i & 1;
        const int ri = i - (i / 3) * 3;   // i % 3
        const uint32_t aB = a_core + b * 9216;
        const uint32_t wB = sb + OFF_WR + ri * 9216 + b_core;
#pragma unroll
        for (int ks = 0; ks < 4; ks++) {
            uint32_t a0, a1, a2, a3;
            LDM4(a0, a1, a2, a3, aB + ks * 32);
#pragma unroll
            for (int jt = 0; jt < 2; jt++) {
                uint32_t r0, r1, r2, r3;
                LDM4(r0, r1, r2, r3, wB + jt * 16 * ROWB + ks * 32);
                mma_f16(acc[2 * jt],     a0, a1, a2, a3, r0, r1);
                mma_f16(acc[2 * jt + 1], a0, a1, a2, a3, r2, r3);
            }
        }
        if (i + 1 < 12) {
            uint32_t* xd = (uint32_t*)(smc + OFF_XS + ((i + 1) & 1) * 9216 + r * ROWB + s * 32);
#pragma unroll
            for (int q = 0; q < 4; q++) {
                xd[2 * q]     = pack2(xr[q].x, xr[q].y);
                xd[2 * q + 1] = pack2(xr[q].z, xr[q].w);
            }
        }
        if (i < 10) CP_WAIT1(); else CP_WAIT0();
        __syncthreads();
    }

    // ---- epilogue1: Hs = fp16(relu(acc + b1)) ----
#pragma unroll
    for (int nt = 0; nt < 4; nt++) {
        const int c = nw * 32 + nt * 8 + 2 * tig;
        float v0 = acc[nt][0] + b1s[c];
        float v1 = acc[nt][1] + b1s[c + 1];
        float v2 = acc[nt][2] + b1s[c];
        float v3 = acc[nt][3] + b1s[c + 1];
        *(uint32_t*)(smc + (mw * 16 + g) * ROWB + c * 2) =
            pack2(v0 > 0.f ? v0 : 0.f, v1 > 0.f ? v1 : 0.f);
        *(uint32_t*)(smc + (mw * 16 + g + 8) * ROWB + c * 2) =
            pack2(v2 > 0.f ? v2 : 0.f, v3 > 0.f ? v3 : 0.f);
    }

    // ---- W2 chunks 0,1 into ring slots 0,1 (all W1 groups drained) ----
    {
        cpa16(wr_dst + 0,  w2_src + 0);
        cpa16(wr_dst + 16, w2_src + 8);
        CP_COMMIT();                                   // g0 = W2 chunk 0
        const __half* ws = w2_src + 64 * H;
        cpa16(wr_dst + 9216 + 0,  ws + 0);
        cpa16(wr_dst + 9216 + 16, ws + 8);
        CP_COMMIT();                                   // g1 = W2 chunk 1
    }
    CP_WAIT1();
    __syncthreads();   // Hs visible + ring0 ready

    // ---- A-fragments of h: loaded once ----
    uint32_t ha[4][4];
#pragma unroll
    for (int ks = 0; ks < 4; ks++)
        LDM4(ha[ks][0], ha[ks][1], ha[ks][2], ha[ks][3], h_core + ks * 32);

    // per-thread row contexts for epilogue2 (rowI clamped -> loads always safe)
    const int rlo = mw * 16 + g, rhi = rlo + 8;
    const bool vlo = rlo < nrows, vhi = rhi < nrows;
    const float* xlo = x + (size_t)rowI[rlo] * D;
    const float* xhi = x + (size_t)rowI[rhi] * D;
    float* olo = out + (size_t)rowI[rlo] * D;
    float* ohi = out + (size_t)rowI[rhi] * D;

    // ============ GEMM2: out = x + h @ W2^T + b2, 12 N-chunks of 64 ============
    rc = 2;
#pragma unroll 1
    for (int j = 0; j < 12; j++) {
        if (j + 2 < 12) {
            const __half* ws = w2_src + (size_t)(j + 2) * 64 * H;
            const uint32_t wd = wr_dst + rc * 9216;
            cpa16(wd + 0, ws + 0);
            cpa16(wd + 16, ws + 8);
            CP_COMMIT();
            rc = (rc == 2) ? 0 : rc + 1;
        }
        // prefetch epilogue x fragments BEFORE the MMA block (hidden by compute)
        float2 xel[4], xeh[4];
#pragma unroll
        for (int nt = 0; nt < 4; nt++) {
            const int cl = j * 64 + nw * 32 + nt * 8 + 2 * tig;
            xel[nt] = *(const float2*)(xlo + cl);
            xeh[nt] = *(const float2*)(xhi + cl);
        }

        float acc2[4][4];
#pragma unroll
        for (int nt = 0; nt < 4; nt++)
#pragma unroll
            for (int q = 0; q < 4; q++) acc2[nt][q] = 0.f;

        const int rj = j - (j / 3) * 3;   // j % 3
        const uint32_t wB = sb + OFF_WR + rj * 9216 + b_core;
#pragma unroll
        for (int ks = 0; ks < 4; ks++) {
#pragma unroll
            for (int jt = 0; jt < 2; jt++) {
                uint32_t r0, r1, r2, r3;
                LDM4(r0, r1, r2, r3, wB + jt * 16 * ROWB + ks * 32);
                mma_f16(acc2[2 * jt],     ha[ks][0], ha[ks][1], ha[ks][2], ha[ks][3], r0, r1);
                mma_f16(acc2[2 * jt + 1], ha[ks][0], ha[ks][1], ha[ks][2], ha[ks][3], r2, r3);
            }
        }

        // fused epilogue: out = x + y + b2
#pragma unroll
        for (int nt = 0; nt < 4; nt++) {
            const int cl = j * 64 + nw * 32 + nt * 8 + 2 * tig;
            float2 bv = *(const float2*)(b2s + cl);
            if (vlo) {
                float2 o = make_float2(xel[nt].x + acc2[nt][0] + bv.x,
                                       xel[nt].y + acc2[nt][1] + bv.y);
                *(float2*)(olo + cl) = o;
            }
            if (vhi) {
                float2 o = make_float2(xeh[nt].x + acc2[nt][2] + bv.x,
                                       xeh[nt].y + acc2[nt][3] + bv.y);
                *(float2*)(ohi + cl) = o;
            }
        }
        if (j < 10) CP_WAIT1(); else CP_WAIT0();
        __syncthreads();
    }
}

extern "C" void kernel_launch(void* const* d_in, const int* in_sizes, int n_in,
                              void* d_out, int out_size)
{
    const float* x   = (const float*)d_in[0];
    const void*  ids = d_in[1];
    const float* W1  = (const float*)d_in[2];
    const float* b1  = (const float*)d_in[3];
    const float* W2  = (const float*)d_in[4];
    const float* b2  = (const float*)d_in[5];
    float*       out = (float*)d_out;

    const int B = in_sizes[1];

    k_histscan<<<NHB, 256>>>(ids, B);
    k_fuse<<<NHB + 336, 256>>>(ids, B, W1, W2);

    cudaFuncSetAttribute(k_main, cudaFuncAttributeMaxDynamicSharedMemorySize, SMEM_BYTES);
    dim3 grid((B + 63) / 64, E);
    k_main<<<grid, 256, SMEM_BYTES>>>(x, b1, b2, out);
}

// round 14
// speedup vs baseline: 1.7357x; 1.0577x over previous
#include <cuda_runtime.h>
#include <cuda_fp16.h>
#include <stdint.h>

#define D 768
#define H 64
#define E 7
#define BMAX 32768
#define NHB 64

// ---------------- device scratch ----------------
__device__ int d_offsets[E + 1];
__device__ int d_cursor[E];
__device__ int d_blk[NHB * E];
__device__ int d_perm[BMAX];
__device__ int d_tick;
__device__ volatile int d_flag;
__device__ __align__(16) __half d_w1t[E * H * D];   // [e][n(H)][k(D)] fp16
__device__ __align__(16) __half d_w2t[E * D * H];   // [e][n(D)][k(H)] fp16

// ---------------- helpers ----------------
__device__ __forceinline__ uint32_t smem_u32(const void* p) {
    uint32_t a;
    asm("{ .reg .u64 t; cvta.to.shared.u64 t, %1; cvt.u32.u64 %0, t; }" : "=r"(a) : "l"(p));
    return a;
}
__device__ __forceinline__ uint32_t pack2(float a, float b) {
    __half2 h = __floats2half2_rn(a, b);
    return *(uint32_t*)&h;
}
__device__ __forceinline__ void cpa16(uint32_t dst, const void* src) {
    asm volatile("cp.async.cg.shared.global [%0], [%1], 16;" :: "r"(dst), "l"(src));
}
#define CP_COMMIT() asm volatile("cp.async.commit_group;" ::: "memory")
#define CP_WAIT1()  asm volatile("cp.async.wait_group 1;" ::: "memory")
#define CP_WAIT0()  asm volatile("cp.async.wait_group 0;" ::: "memory")
#define LDM4(r0, r1, r2, r3, addr) \
    asm volatile("ldmatrix.sync.aligned.m8n8.x4.shared.b16 {%0,%1,%2,%3}, [%4];" \
        : "=r"(r0), "=r"(r1), "=r"(r2), "=r"(r3) : "r"(addr))

__device__ __forceinline__ void mma_f16(float* c, uint32_t a0, uint32_t a1, uint32_t a2,
                                        uint32_t a3, uint32_t b0, uint32_t b1) {
    asm volatile(
        "mma.sync.aligned.m16n8k16.row.col.f32.f16.f16.f32 "
        "{%0,%1,%2,%3}, {%4,%5,%6,%7}, {%8,%9}, {%0,%1,%2,%3};\n"
        : "+f"(c[0]), "+f"(c[1]), "+f"(c[2]), "+f"(c[3])
        : "r"(a0), "r"(a1), "r"(a2), "r"(a3), "r"(b0), "r"(b1));
}
__device__ __forceinline__ int load_id(const void* ids, int i, int is64) {
    return is64 ? (int)((const long long*)ids)[i] : ((const int*)ids)[i];
}

// ---------------- launch 1: fused hist + scan + scatter + weight transpose ----------------
// blocks [0,64): histogram -> ticket -> (last) scan -> flag -> scatter
// blocks [64,736): 672 independent 32x32 transpose tiles (run concurrently)
__global__ void __launch_bounds__(256) k_prep(const void* __restrict__ ids, int B,
                                              const float* __restrict__ W1,
                                              const float* __restrict__ W2) {
    const int blk = blockIdx.x;
    const int t = threadIdx.x;
    if (blk < NHB) {
        __shared__ int sc[E];
        __shared__ int sbad;
        __shared__ int ticket;
        if (t < E) sc[t] = 0;
        if (t == 0) sbad = 0;
        __syncthreads();
        {   // dtype probe: int64 ids all in [0,E); int32 viewed as int64 fails w.p. ~1
            const long long* p = (const long long*)ids;
            int n = min(B / 2, 256);
            if (t < n) { long long v = p[t]; if (v < 0 || v >= E) sbad = 1; }
        }
        __syncthreads();
        const int is64 = !sbad;
        for (int i = blk * 256 + t; i < B; i += NHB * 256) {
            int e = load_id(ids, i, is64);
            if ((unsigned)e < E) atomicAdd(&sc[e], 1);
        }
        __syncthreads();
        if (t < E) d_blk[blk * E + t] = sc[t];
        __threadfence();
        if (t == 0) ticket = atomicAdd(&d_tick, 1);
        __syncthreads();
        if (ticket == NHB - 1 && t == 0) {
            int a = 0;
            for (int e = 0; e < E; e++) {
                int s = 0;
                for (int b = 0; b < NHB; b++) s += d_blk[b * E + e];
                d_offsets[e] = a; d_cursor[e] = a; a += s;
            }
            d_offsets[E] = a;
            d_tick = 0;
            __threadfence();
            d_flag = 1;
        }
        // spin until offsets/cursors published (all 736 blocks co-resident: capacity 1184)
        if (t == 0) { while (d_flag == 0) {} }
        __syncthreads();
        __threadfence();
        for (int i = blk * 256 + t; i < B; i += NHB * 256) {
            int e = load_id(ids, i, is64);
            if ((unsigned)e < E) {
                int p = atomicAdd(&d_cursor[e], 1);
                d_perm[p] = i;
            }
        }
    } else {
        __shared__ float ts[32][33];
        const int tx = t & 31, ty = t >> 5;
        const int tile = blk - NHB;   // [0,672)
        const float* src;
        __half* dst;
        int k0, n0, srcLD, dstLD;
        if (tile < 336) {           // W1 [D][H] -> w1t [H][D]
            int e = tile / 48, r = tile % 48;
            k0 = (r >> 1) * 32; n0 = (r & 1) * 32;
            src = W1 + (size_t)e * D * H;  srcLD = H;
            dst = d_w1t + (size_t)e * H * D; dstLD = D;
        } else {                    // W2 [H][D] -> w2t [D][H]
            int t2 = tile - 336;
            int e = t2 / 48, r = t2 % 48;
            k0 = (r / 24) * 32; n0 = (r % 24) * 32;
            src = W2 + (size_t)e * H * D;  srcLD = D;
            dst = d_w2t + (size_t)e * D * H; dstLD = H;
        }
#pragma unroll
        for (int p = 0; p < 4; p++)
            ts[ty + 8 * p][tx] = src[(size_t)(k0 + ty + 8 * p) * srcLD + n0 + tx];
        __syncthreads();
#pragma unroll
        for (int p = 0; p < 4; p++)
            dst[(size_t)(n0 + ty + 8 * p) * dstLD + k0 + tx] =
                __float2half(ts[tx][ty + 8 * p]);
    }
}

// ---------------- smem layout (bytes) ----------------
// Hs        @ 0     : 9216
// Xs[2]     @ 9216  : 18432
// Wring[3]  @ 27648 : 27648
// b1s f32   @ 55296 : 256
// b2s f32   @ 55552 : 3072
// rowI int  @ 58624 : 256
#define ROWB 144
#define OFF_XS 9216
#define OFF_WR 27648
#define SMEM_BYTES 58880

__device__ __forceinline__ void ldg_x(float4 xr[4], const float* src) {
#pragma unroll
    for (int q = 0; q < 4; q++) xr[q] = __ldg((const float4*)src + q);
}
__device__ __forceinline__ void sts_x(char* dst, const float4 xr[4]) {
    uint32_t* xd = (uint32_t*)dst;
#pragma unroll
    for (int q = 0; q < 4; q++) {
        xd[2 * q]     = pack2(xr[q].x, xr[q].y);
        xd[2 * q + 1] = pack2(xr[q].z, xr[q].w);
    }
}
__device__ __forceinline__ void g1_chunk(float acc[4][4], uint32_t aB, uint32_t wB) {
#pragma unroll
    for (int ks = 0; ks < 4; ks++) {
        uint32_t a0, a1, a2, a3;
        LDM4(a0, a1, a2, a3, aB + ks * 32);
#pragma unroll
        for (int jt = 0; jt < 2; jt++) {
            uint32_t r0, r1, r2, r3;
            LDM4(r0, r1, r2, r3, wB + jt * 16 * ROWB + ks * 32);
            mma_f16(acc[2 * jt],     a0, a1, a2, a3, r0, r1);
            mma_f16(acc[2 * jt + 1], a0, a1, a2, a3, r2, r3);
        }
    }
}

// ---------------- launch 2: main kernel (8 warps, 3-stage W ring, dist-2 X) ----------------
__global__ void __launch_bounds__(256)
k_main(const float* __restrict__ x, const float* __restrict__ b1,
       const float* __restrict__ b2, float* __restrict__ out)
{
    // reset prep flag for the next graph replay (stream-ordered after k_prep)
    if (blockIdx.x == 0 && blockIdx.y == 0 && threadIdx.x == 0) d_flag = 0;

    const int e = blockIdx.y;
    const int seg0 = d_offsets[e], seg1 = d_offsets[e + 1];
    const int row0 = seg0 + blockIdx.x * 64;
    if (row0 >= seg1) return;
    const int nrows = min(64, seg1 - row0);

    extern __shared__ char smc[];
    const uint32_t sb = smem_u32(smc);
    float* b1s = (float*)(smc + 55296);
    float* b2s = (float*)(smc + 55552);
    int*   rowI = (int*)(smc + 58624);

    const int tid = threadIdx.x, w = tid >> 5, lane = tid & 31;
    const int mw = w & 3, nw = w >> 2;
    const int g = lane >> 2, tig = lane & 3;

    if (tid < 64) {
        rowI[tid] = d_perm[row0 + min(tid, nrows - 1)];
        b1s[tid] = b1[e * H + tid];
    }
    for (int i = tid; i < D; i += 256) b2s[i] = b2[e * D + i];
    __syncthreads();

    const __half* W1e = d_w1t + (size_t)e * H * D;
    const __half* W2e = d_w2t + (size_t)e * D * H;

    // loaders: r = n-row (0..63), s = 16-element segment (0..3)
    const int r = tid >> 2, s = tid & 3;
    const float* xg = x + (size_t)rowI[r] * D + s * 16;
    const __half* w1_src = W1e + r * D + s * 16;
    const __half* w2_src = W2e + r * H + s * 16;
    const uint32_t wr_dst = sb + OFF_WR + r * ROWB + s * 32;   // + ring*9216
    char* const x_buf0 = smc + OFF_XS + r * ROWB + s * 32;
    char* const x_buf1 = x_buf0 + 9216;

    // fragment address cores
    const uint32_t a_core = sb + OFF_XS + (mw * 16 + (lane & 15)) * ROWB + ((lane >> 4) & 1) * 16;
    const uint32_t h_core = sb + (mw * 16 + (lane & 15)) * ROWB + ((lane >> 4) & 1) * 16;
    const uint32_t b_core = (nw * 32 + (lane & 7) + ((lane >> 4) & 1) * 8) * ROWB
                          + ((lane >> 3) & 1) * 16;

    // ---- prologue: c0->buf0; c1->xrO; c2->xrE; W1 slots 0,1 committed ----
    float4 xrE[4], xrO[4];
    ldg_x(xrE, xg);                                  // c0
    cpa16(wr_dst + 0,  w1_src + 0);
    cpa16(wr_dst + 16, w1_src + 8);
    CP_COMMIT();                                     // W1 c0 -> slot0
    cpa16(wr_dst + 9216 + 0,  w1_src + 64 + 0);
    cpa16(wr_dst + 9216 + 16, w1_src + 64 + 8);
    CP_COMMIT();                                     // W1 c1 -> slot1
    sts_x(x_buf0, xrE);                              // c0 -> buf0
    ldg_x(xrO, xg + 64);                             // c1
    ldg_x(xrE, xg + 128);                            // c2 (xrE free after STS)
    CP_WAIT1();                                      // slot0 ready
    __syncthreads();

    // ============ GEMM1: h = relu(X @ W1^T + b1), 12 K-chunks of 64 ============
    // iter i: STS c(i+1) (loaded 2 iters ago), LDG c(i+3), commit W c(i+2)
    //         -> slot (i+2)%3 (free: c(i-1) done), compute c(i) from slot i%3.
    float acc[4][4];
#pragma unroll
    for (int nt = 0; nt < 4; nt++)
#pragma unroll
        for (int q = 0; q < 4; q++) acc[nt][q] = 0.f;

    int rc = 2;  // ring slot for chunk i+2 (c2 -> slot2)
    int ri = 0;  // ring slot of current chunk (c0 -> slot0)
#pragma unroll 1
    for (int ii = 0; ii < 6; ii++) {
        const int i0 = 2 * ii, i1 = i0 + 1;
        // ---- even sub-iter i0: compute buf0 ----
        sts_x(x_buf1, xrO);                          // c(i0+1) -> buf1
        if (i0 + 3 < 12) ldg_x(xrO, xg + (i0 + 3) * 64);
        if (i0 + 2 < 12) {
            const __half* ws = w1_src + (i0 + 2) * 64;
            const uint32_t wd = wr_dst + rc * 9216;
            cpa16(wd + 0, ws + 0);
            cpa16(wd + 16, ws + 8);
            CP_COMMIT();
            rc = (rc == 2) ? 0 : rc + 1;
        }
        g1_chunk(acc, a_core, sb + OFF_WR + ri * 9216 + b_core);
        ri = (ri == 2) ? 0 : ri + 1;
        if (i0 < 10) CP_WAIT1(); else CP_WAIT0();
        __syncthreads();
        // ---- odd sub-iter i1: compute buf1 ----
        if (i1 + 1 < 12) sts_x(x_buf0, xrE);         // c(i1+1) -> buf0
        if (i1 + 3 < 12) ldg_x(xrE, xg + (i1 + 3) * 64);
        if (i1 + 2 < 12) {
            const __half* ws = w1_src + (i1 + 2) * 64;
            const uint32_t wd = wr_dst + rc * 9216;
            cpa16(wd + 0, ws + 0);
            cpa16(wd + 16, ws + 8);
            CP_COMMIT();
            rc = (rc == 2) ? 0 : rc + 1;
        }
        g1_chunk(acc, a_core + 9216, sb + OFF_WR + ri * 9216 + b_core);
        ri = (ri == 2) ? 0 : ri + 1;
        if (i1 < 10) CP_WAIT1(); else CP_WAIT0();
        __syncthreads();
    }

    // ---- epilogue1: Hs = fp16(relu(acc + b1)) ----
#pragma unroll
    for (int nt = 0; nt < 4; nt++) {
        const int c = nw * 32 + nt * 8 + 2 * tig;
        float v0 = acc[nt][0] + b1s[c];
        float v1 = acc[nt][1] + b1s[c + 1];
        float v2 = acc[nt][2] + b1s[c];
        float v3 = acc[nt][3] + b1s[c + 1];
        *(uint32_t*)(smc + (mw * 16 + g) * ROWB + c * 2) =
            pack2(v0 > 0.f ? v0 : 0.f, v1 > 0.f ? v1 : 0.f);
        *(uint32_t*)(smc + (mw * 16 + g + 8) * ROWB + c * 2) =
            pack2(v2 > 0.f ? v2 : 0.f, v3 > 0.f ? v3 : 0.f);
    }

    // ---- W2 chunks 0,1 into ring slots 0,1 (all W1 groups drained) ----
    {
        cpa16(wr_dst + 0,  w2_src + 0);
        cpa16(wr_dst + 16, w2_src + 8);
        CP_COMMIT();                                 // W2 c0 -> slot0
        const __half* ws = w2_src + 64 * H;
        cpa16(wr_dst + 9216 + 0,  ws + 0);
        cpa16(wr_dst + 9216 + 16, ws + 8);
        CP_COMMIT();                                 // W2 c1 -> slot1
    }
    CP_WAIT1();
    __syncthreads();   // Hs visible + ring0 ready

    // ---- A-fragments of h: loaded once ----
    uint32_t ha[4][4];
#pragma unroll
    for (int ks = 0; ks < 4; ks++)
        LDM4(ha[ks][0], ha[ks][1], ha[ks][2], ha[ks][3], h_core + ks * 32);

    // per-thread row contexts for epilogue2 (rowI clamped -> loads always safe)
    const int rlo = mw * 16 + g, rhi = rlo + 8;
    const bool vlo = rlo < nrows, vhi = rhi < nrows;
    const float* xlo = x + (size_t)rowI[rlo] * D;
    const float* xhi = x + (size_t)rowI[rhi] * D;
    float* olo = out + (size_t)rowI[rlo] * D;
    float* ohi = out + (size_t)rowI[rhi] * D;

    // ============ GEMM2: out = x + h @ W2^T + b2, 12 N-chunks of 64 ============
    rc = 2;
#pragma unroll 1
    for (int j = 0; j < 12; j++) {
        if (j + 2 < 12) {
            const __half* ws = w2_src + (size_t)(j + 2) * 64 * H;
            const uint32_t wd = wr_dst + rc * 9216;
            cpa16(wd + 0, ws + 0);
            cpa16(wd + 16, ws + 8);
            CP_COMMIT();
            rc = (rc == 2) ? 0 : rc + 1;
        }
        // prefetch epilogue x fragments BEFORE the MMA block (hidden by compute)
        float2 xel[4], xeh[4];
#pragma unroll
        for (int nt = 0; nt < 4; nt++) {
            const int cl = j * 64 + nw * 32 + nt * 8 + 2 * tig;
            xel[nt] = *(const float2*)(xlo + cl);
            xeh[nt] = *(const float2*)(xhi + cl);
        }

        float acc2[4][4];
#pragma unroll
        for (int nt = 0; nt < 4; nt++)
#pragma unroll
            for (int q = 0; q < 4; q++) acc2[nt][q] = 0.f;

        const int rj = j - (j / 3) * 3;   // j % 3
        const uint32_t wB = sb + OFF_WR + rj * 9216 + b_core;
#pragma unroll
        for (int ks = 0; ks < 4; ks++) {
#pragma unroll
            for (int jt = 0; jt < 2; jt++) {
                uint32_t r0, r1, r2, r3;
                LDM4(r0, r1, r2, r3, wB + jt * 16 * ROWB + ks * 32);
                mma_f16(acc2[2 * jt],     ha[ks][0], ha[ks][1], ha[ks][2], ha[ks][3], r0, r1);
                mma_f16(acc2[2 * jt + 1], ha[ks][0], ha[ks][1], ha[ks][2], ha[ks][3], r2, r3);
            }
        }

        // fused epilogue: out = x + y + b2
#pragma unroll
        for (int nt = 0; nt < 4; nt++) {
            const int cl = j * 64 + nw * 32 + nt * 8 + 2 * tig;
            float2 bv = *(const float2*)(b2s + cl);
            if (vlo) {
                float2 o = make_float2(xel[nt].x + acc2[nt][0] + bv.x,
                                       xel[nt].y + acc2[nt][1] + bv.y);
                *(float2*)(olo + cl) = o;
            }
            if (vhi) {
                float2 o = make_float2(xeh[nt].x + acc2[nt][2] + bv.x,
                                       xeh[nt].y + acc2[nt][3] + bv.y);
                *(float2*)(ohi + cl) = o;
            }
        }
        if (j < 10) CP_WAIT1(); else CP_WAIT0();
        __syncthreads();
    }
}

extern "C" void kernel_launch(void* const* d_in, const int* in_sizes, int n_in,
                              void* d_out, int out_size)
{
    const float* x   = (const float*)d_in[0];
    const void*  ids = d_in[1];
    const float* W1  = (const float*)d_in[2];
    const float* b1  = (const float*)d_in[3];
    const float* W2  = (const float*)d_in[4];
    const float* b2  = (const float*)d_in[5];
    float*       out = (float*)d_out;

    const int B = in_sizes[1];

    k_prep<<<NHB + 672, 256>>>(ids, B, W1, W2);

    cudaFuncSetAttribute(k_main, cudaFuncAttributeMaxDynamicSharedMemorySize, SMEM_BYTES);
    dim3 grid((B + 63) / 64, E);
    k_main<<<grid, 256, SMEM_BYTES>>>(x, b1, b2, out);
}

// round 15
// speedup vs baseline: 1.8691x; 1.0769x over previous
#include <cuda_runtime.h>
#include <cuda_fp16.h>
#include <stdint.h>

#define D 768
#define H 64
#define E 7
#define BMAX 32768
#define NHB 64
#define CPE 21            // CTAs per expert

// ---------------- device scratch ----------------
__device__ int d_offsets[E + 1];
__device__ int d_cursor[E];
__device__ int d_blk[NHB * E];
__device__ int d_perm[BMAX];
__device__ int d_tick;
__device__ volatile int d_flag;
__device__ __align__(16) __half d_w1t[E * H * D];   // [e][n(H)][k(D)] fp16
__device__ __align__(16) __half d_w2t[E * D * H];   // [e][n(D)][k(H)] fp16
__device__ __align__(16) __half d_h[BMAX * H];      // h scratch (zero-init)

// ---------------- helpers ----------------
__device__ __forceinline__ uint32_t smem_u32(const void* p) {
    uint32_t a;
    asm("{ .reg .u64 t; cvta.to.shared.u64 t, %1; cvt.u32.u64 %0, t; }" : "=r"(a) : "l"(p));
    return a;
}
__device__ __forceinline__ uint32_t pack2(float a, float b) {
    __half2 h = __floats2half2_rn(a, b);
    return *(uint32_t*)&h;
}
__device__ __forceinline__ void cpa16(uint32_t dst, const void* src) {
    asm volatile("cp.async.cg.shared.global [%0], [%1], 16;" :: "r"(dst), "l"(src));
}
#define CP_COMMIT() asm volatile("cp.async.commit_group;" ::: "memory")
#define CP_WAIT0()  asm volatile("cp.async.wait_group 0;" ::: "memory")
#define LDM4(r0, r1, r2, r3, addr) \
    asm volatile("ldmatrix.sync.aligned.m8n8.x4.shared.b16 {%0,%1,%2,%3}, [%4];" \
        : "=r"(r0), "=r"(r1), "=r"(r2), "=r"(r3) : "r"(addr))

__device__ __forceinline__ void mma_f16(float* c, uint32_t a0, uint32_t a1, uint32_t a2,
                                        uint32_t a3, uint32_t b0, uint32_t b1) {
    asm volatile(
        "mma.sync.aligned.m16n8k16.row.col.f32.f16.f16.f32 "
        "{%0,%1,%2,%3}, {%4,%5,%6,%7}, {%8,%9}, {%0,%1,%2,%3};\n"
        : "+f"(c[0]), "+f"(c[1]), "+f"(c[2]), "+f"(c[3])
        : "r"(a0), "r"(a1), "r"(a2), "r"(a3), "r"(b0), "r"(b1));
}
__device__ __forceinline__ int load_id(const void* ids, int i, int is64) {
    return is64 ? (int)((const long long*)ids)[i] : ((const int*)ids)[i];
}
__device__ __forceinline__ void ldg_x(float4 xr[4], const float* src) {
#pragma unroll
    for (int q = 0; q < 4; q++) xr[q] = __ldg((const float4*)src + q);
}
__device__ __forceinline__ void sts_x(char* dst, const float4 xr[4]) {
    uint32_t* xd = (uint32_t*)dst;
#pragma unroll
    for (int q = 0; q < 4; q++) {
        xd[2 * q]     = pack2(xr[q].x, xr[q].y);
        xd[2 * q + 1] = pack2(xr[q].z, xr[q].w);
    }
}

// ---------------- launch 1: fused hist + scan + scatter + weight transpose ----------------
__global__ void __launch_bounds__(256) k_prep(const void* __restrict__ ids, int B,
                                              const float* __restrict__ W1,
                                              const float* __restrict__ W2) {
    const int blk = blockIdx.x;
    const int t = threadIdx.x;
    if (blk < NHB) {
        __shared__ int sc[E];
        __shared__ int sbad;
        __shared__ int ticket;
        if (t < E) sc[t] = 0;
        if (t == 0) sbad = 0;
        __syncthreads();
        {   // dtype probe
            const long long* p = (const long long*)ids;
            int n = min(B / 2, 256);
            if (t < n) { long long v = p[t]; if (v < 0 || v >= E) sbad = 1; }
        }
        __syncthreads();
        const int is64 = !sbad;
        for (int i = blk * 256 + t; i < B; i += NHB * 256) {
            int e = load_id(ids, i, is64);
            if ((unsigned)e < E) atomicAdd(&sc[e], 1);
        }
        __syncthreads();
        if (t < E) d_blk[blk * E + t] = sc[t];
        __threadfence();
        if (t == 0) ticket = atomicAdd(&d_tick, 1);
        __syncthreads();
        if (ticket == NHB - 1 && t == 0) {
            int a = 0;
            for (int e = 0; e < E; e++) {
                int s = 0;
                for (int b = 0; b < NHB; b++) s += d_blk[b * E + e];
                d_offsets[e] = a; d_cursor[e] = a; a += s;
            }
            d_offsets[E] = a;
            d_tick = 0;
            __threadfence();
            d_flag = 1;
        }
        if (t == 0) { while (d_flag == 0) {} }
        __syncthreads();
        __threadfence();
        for (int i = blk * 256 + t; i < B; i += NHB * 256) {
            int e = load_id(ids, i, is64);
            if ((unsigned)e < E) {
                int p = atomicAdd(&d_cursor[e], 1);
                d_perm[p] = i;
            }
        }
    } else {
        __shared__ float ts[32][33];
        const int tx = t & 31, ty = t >> 5;
        const int tile = blk - NHB;
        const float* src;
        __half* dst;
        int k0, n0, srcLD, dstLD;
        if (tile < 336) {           // W1 [D][H] -> w1t [H][D]
            int e = tile / 48, r = tile % 48;
            k0 = (r >> 1) * 32; n0 = (r & 1) * 32;
            src = W1 + (size_t)e * D * H;  srcLD = H;
            dst = d_w1t + (size_t)e * H * D; dstLD = D;
        } else {                    // W2 [H][D] -> w2t [D][H]
            int t2 = tile - 336;
            int e = t2 / 48, r = t2 % 48;
            k0 = (r / 24) * 32; n0 = (r % 24) * 32;
            src = W2 + (size_t)e * H * D;  srcLD = D;
            dst = d_w2t + (size_t)e * D * H; dstLD = H;
        }
#pragma unroll
        for (int p = 0; p < 4; p++)
            ts[ty + 8 * p][tx] = src[(size_t)(k0 + ty + 8 * p) * srcLD + n0 + tx];
        __syncthreads();
#pragma unroll
        for (int p = 0; p < 4; p++)
            dst[(size_t)(n0 + ty + 8 * p) * dstLD + k0 + tx] =
                __float2half(ts[tx][ty + 8 * p]);
    }
}

// ---------------- kernel A: h = relu(x @ W1^T + b1), W1 resident ----------------
#define ROWB 144
#define W1LD 1552
#define A_W1 0
#define A_XS 99328
#define A_B1 136192
#define A_RI 136448
#define A_SMEM 136960

__device__ __forceinline__ void gA_chunk(float acc[4][4], uint32_t aB, uint32_t wB) {
#pragma unroll
    for (int ks = 0; ks < 4; ks++) {
        uint32_t a0, a1, a2, a3;
        LDM4(a0, a1, a2, a3, aB + ks * 32);
#pragma unroll
        for (int jt = 0; jt < 2; jt++) {
            uint32_t r0, r1, r2, r3;
            LDM4(r0, r1, r2, r3, wB + jt * 16 * W1LD + ks * 32);
            mma_f16(acc[2 * jt],     a0, a1, a2, a3, r0, r1);
            mma_f16(acc[2 * jt + 1], a0, a1, a2, a3, r2, r3);
        }
    }
}

__global__ void __launch_bounds__(512)
k_g1(const float* __restrict__ x, const float* __restrict__ b1)
{
    if (blockIdx.x == 0 && blockIdx.y == 0 && threadIdx.x == 0) d_flag = 0;

    const int e = blockIdx.y, cta = blockIdx.x;
    const int seg0 = d_offsets[e], seg1 = d_offsets[e + 1];
    const int ntiles = (seg1 - seg0 + 127) >> 7;

    extern __shared__ char smc[];
    const uint32_t sb = smem_u32(smc);
    float* b1s = (float*)(smc + A_B1);
    int* rowI = (int*)(smc + A_RI);

    const int tid = threadIdx.x, w = tid >> 5, lane = tid & 31;
    const int mw = w & 7, nw = w >> 3;
    const int g = lane >> 2, tig = lane & 3;

    // ---- resident W1 (64 n-rows x 768 k halfs, ROWB 1552) via cp.async ----
    {
        const __half* W1e = d_w1t + (size_t)e * H * D;
        const int r = tid >> 3, sg = tid & 7;
        const uint32_t dst = sb + A_W1 + r * W1LD + sg * 192;
        const __half* src = W1e + r * D + sg * 96;
#pragma unroll
        for (int q = 0; q < 12; q++) cpa16(dst + q * 16, src + q * 8);
        CP_COMMIT();
    }
    if (tid < H) b1s[tid] = b1[e * H + tid];

    const uint32_t a_core = sb + A_XS + (mw * 16 + (lane & 15)) * ROWB + ((lane >> 4) & 1) * 16;
    const uint32_t b_core = sb + A_W1 + (nw * 32 + (lane & 7) + ((lane >> 4) & 1) * 8) * W1LD
                          + ((lane >> 3) & 1) * 16;
    const int xr_ = tid >> 2, xs_ = tid & 3;
    char* const xb0 = smc + A_XS + xr_ * ROWB + xs_ * 32;
    char* const xb1 = xb0 + 18432;

#pragma unroll 1
    for (int tile = cta; tile < ntiles; tile += CPE) {
        const int row0 = seg0 + tile * 128;
        const int nrows = min(128, seg1 - row0);
        __syncthreads();                 // protect rowI/Xs rewrite (prev tile done)
        if (tid < 128) rowI[tid] = d_perm[row0 + min(tid, nrows - 1)];
        __syncthreads();
        const float* xg = x + (size_t)rowI[xr_] * D + xs_ * 16;

        // dist-2 X prologue: c0->buf0, c1->xrO, c2->xrE
        float4 xrE[4], xrO[4];
        ldg_x(xrE, xg);
        sts_x(xb0, xrE);
        ldg_x(xrO, xg + 64);
        ldg_x(xrE, xg + 128);
        CP_WAIT0();                      // W1 resident (no-op after first tile)
        __syncthreads();

        float acc[4][4];
#pragma unroll
        for (int nt = 0; nt < 4; nt++)
#pragma unroll
            for (int q = 0; q < 4; q++) acc[nt][q] = 0.f;

#pragma unroll 1
        for (int ii = 0; ii < 6; ii++) {
            const int i0 = 2 * ii, i1 = i0 + 1;
            sts_x(xb1, xrO);                               // c(i0+1)
            if (i0 + 3 < 12) ldg_x(xrO, xg + (i0 + 3) * 64);
            gA_chunk(acc, a_core, b_core + i0 * 128);
            __syncthreads();
            if (i1 + 1 < 12) sts_x(xb0, xrE);              // c(i1+1)
            if (i1 + 3 < 12) ldg_x(xrE, xg + (i1 + 3) * 64);
            gA_chunk(acc, a_core + 18432, b_core + i1 * 128);
            __syncthreads();
        }

        // h = fp16(relu(acc + b1)) -> gmem scratch (guarded rows)
        const int rlo = mw * 16 + g, rhi = rlo + 8;
#pragma unroll
        for (int nt = 0; nt < 4; nt++) {
            const int c = nw * 32 + nt * 8 + 2 * tig;
            float v0 = acc[nt][0] + b1s[c];
            float v1 = acc[nt][1] + b1s[c + 1];
            float v2 = acc[nt][2] + b1s[c];
            float v3 = acc[nt][3] + b1s[c + 1];
            uint32_t plo = pack2(v0 > 0.f ? v0 : 0.f, v1 > 0.f ? v1 : 0.f);
            uint32_t phi = pack2(v2 > 0.f ? v2 : 0.f, v3 > 0.f ? v3 : 0.f);
            if (rlo < nrows)
                *(uint32_t*)((char*)d_h + ((size_t)(row0 + rlo) * H + c) * 2) = plo;
            if (rhi < nrows)
                *(uint32_t*)((char*)d_h + ((size_t)(row0 + rhi) * H + c) * 2) = phi;
        }
    }
}

// ---------------- kernel B: out = x + h @ W2^T + b2, W2 resident ----------------
#define B_W2 0
#define B_HB 110592
#define B_B2 129024
#define B_RI 132096
#define B_SMEM 132608

__global__ void __launch_bounds__(512)
k_g2(const float* __restrict__ x, const float* __restrict__ b2,
     float* __restrict__ out)
{
    const int e = blockIdx.y, cta = blockIdx.x;
    const int seg0 = d_offsets[e], seg1 = d_offsets[e + 1];
    const int ntiles = (seg1 - seg0 + 127) >> 7;

    extern __shared__ char smc[];
    const uint32_t sb = smem_u32(smc);
    float* b2s = (float*)(smc + B_B2);
    int* rowI = (int*)(smc + B_RI);

    const int tid = threadIdx.x, w = tid >> 5, lane = tid & 31;
    const int mw = w & 7, nw = w >> 3;
    const int g = lane >> 2, tig = lane & 3;

    // ---- resident W2 (768 n-rows x 64 k halfs, ROWB 144) via cp.async ----
    {
        const __half* W2e = d_w2t + (size_t)e * D * H;
        for (int rr = tid; rr < D; rr += 512) {
            const uint32_t dst = sb + B_W2 + rr * ROWB;
            const __half* src = W2e + rr * H;
#pragma unroll
            for (int q = 0; q < 8; q++) cpa16(dst + q * 16, src + q * 8);
        }
        CP_COMMIT();
    }
    for (int i = tid; i < D; i += 512) b2s[i] = b2[e * D + i];

    const uint32_t h_core = sb + B_HB + (mw * 16 + (lane & 15)) * ROWB + ((lane >> 4) & 1) * 16;
    const uint32_t w_core = sb + B_W2 + ((lane & 7) + ((lane >> 4) & 1) * 8) * ROWB
                          + ((lane >> 3) & 1) * 16;
    const int hr = tid >> 2, hs = tid & 3;

#pragma unroll 1
    for (int tile = cta; tile < ntiles; tile += CPE) {
        const int row0 = seg0 + tile * 128;
        const int nrows = min(128, seg1 - row0);
        __syncthreads();                 // protect rowI/Hb rewrite (prev tile done)
        if (tid < 128) rowI[tid] = d_perm[row0 + min(tid, nrows - 1)];
        {   // h tile cp.async (row-clamped within segment -> in-bounds)
            const int srow = min(row0 + hr, seg1 - 1);
            const __half* src = d_h + (size_t)srow * H + hs * 16;
            const uint32_t dst = sb + B_HB + hr * ROWB + hs * 32;
            cpa16(dst, src);
            cpa16(dst + 16, src + 8);
        }
        CP_COMMIT();
        CP_WAIT0();                      // W2 (first tile) + h tile
        __syncthreads();

        // A-fragments of h for this tile (registers, reused for all 12 N-chunks)
        uint32_t ha[4][4];
#pragma unroll
        for (int ks = 0; ks < 4; ks++)
            LDM4(ha[ks][0], ha[ks][1], ha[ks][2], ha[ks][3], h_core + ks * 32);

        const int rlo = mw * 16 + g, rhi = rlo + 8;
        const bool vlo = rlo < nrows, vhi = rhi < nrows;
        const float* xlo = x + (size_t)rowI[rlo] * D;
        const float* xhi = x + (size_t)rowI[rhi] * D;
        float* olo = out + (size_t)rowI[rlo] * D;
        float* ohi = out + (size_t)rowI[rhi] * D;

        // 12 N-chunks, NO barriers (W2 + h read-only resident)
#pragma unroll 1
        for (int j = 0; j < 12; j++) {
            float2 xel[4], xeh[4];
#pragma unroll
            for (int nt = 0; nt < 4; nt++) {
                const int cl = j * 64 + nw * 32 + nt * 8 + 2 * tig;
                xel[nt] = *(const float2*)(xlo + cl);
                xeh[nt] = *(const float2*)(xhi + cl);
            }
            float acc2[4][4];
#pragma unroll
            for (int nt = 0; nt < 4; nt++)
#pragma unroll
                for (int q = 0; q < 4; q++) acc2[nt][q] = 0.f;

            const uint32_t wB = w_core + (j * 64 + nw * 32) * ROWB;
#pragma unroll
            for (int ks = 0; ks < 4; ks++) {
#pragma unroll
                for (int jt = 0; jt < 2; jt++) {
                    uint32_t r0, r1, r2, r3;
                    LDM4(r0, r1, r2, r3, wB + jt * 16 * ROWB + ks * 32);
                    mma_f16(acc2[2 * jt],     ha[ks][0], ha[ks][1], ha[ks][2], ha[ks][3], r0, r1);
                    mma_f16(acc2[2 * jt + 1], ha[ks][0], ha[ks][1], ha[ks][2], ha[ks][3], r2, r3);
                }
            }
#pragma unroll
            for (int nt = 0; nt < 4; nt++) {
                const int cl = j * 64 + nw * 32 + nt * 8 + 2 * tig;
                float2 bv = *(const float2*)(b2s + cl);
                if (vlo) {
                    float2 o = make_float2(xel[nt].x + acc2[nt][0] + bv.x,
                                           xel[nt].y + acc2[nt][1] + bv.y);
                    *(float2*)(olo + cl) = o;
                }
                if (vhi) {
                    float2 o = make_float2(xeh[nt].x + acc2[nt][2] + bv.x,
                                           xeh[nt].y + acc2[nt][3] + bv.y);
                    *(float2*)(ohi + cl) = o;
                }
            }
        }
    }
}

extern "C" void kernel_launch(void* const* d_in, const int* in_sizes, int n_in,
                              void* d_out, int out_size)
{
    const float* x   = (const float*)d_in[0];
    const void*  ids = d_in[1];
    const float* W1  = (const float*)d_in[2];
    const float* b1  = (const float*)d_in[3];
    const float* W2  = (const float*)d_in[4];
    const float* b2  = (const float*)d_in[5];
    float*       out = (float*)d_out;

    const int B = in_sizes[1];

    k_prep<<<NHB + 672, 256>>>(ids, B, W1, W2);

    cudaFuncSetAttribute(k_g1, cudaFuncAttributeMaxDynamicSharedMemorySize, A_SMEM);
    cudaFuncSetAttribute(k_g2, cudaFuncAttributeMaxDynamicSharedMemorySize, B_SMEM);
    dim3 grid(CPE, E);
    k_g1<<<grid, 512, A_SMEM>>>(x, b1);
    k_g2<<<grid, 512, B_SMEM>>>(x, b2, out);
}

// round 16
// speedup vs baseline: 2.0110x; 1.0759x over previous
#include <cuda_runtime.h>
#include <cuda_fp16.h>
#include <stdint.h>

#define D 768
#define H 64
#define E 7
#define BMAX 32768
#define NHB 64
#define CPE 21            // CTAs per expert

// ---------------- device scratch ----------------
__device__ int d_offsets[E + 1];
__device__ int d_cursor[E];
__device__ int d_blk[NHB * E];
__device__ int d_perm[BMAX];
__device__ int d_tick;
__device__ volatile int d_flag;
__device__ __align__(16) __half d_w1t[E * H * D];   // [e][n(H)][k(D)] fp16
__device__ __align__(16) __half d_w2t[E * D * H];   // [e][n(D)][k(H)] fp16

// ---------------- helpers ----------------
__device__ __forceinline__ uint32_t smem_u32(const void* p) {
    uint32_t a;
    asm("{ .reg .u64 t; cvta.to.shared.u64 t, %1; cvt.u32.u64 %0, t; }" : "=r"(a) : "l"(p));
    return a;
}
__device__ __forceinline__ uint32_t pack2(float a, float b) {
    __half2 h = __floats2half2_rn(a, b);
    return *(uint32_t*)&h;
}
__device__ __forceinline__ void cpa16(uint32_t dst, const void* src) {
    asm volatile("cp.async.cg.shared.global [%0], [%1], 16;" :: "r"(dst), "l"(src));
}
#define CP_COMMIT() asm volatile("cp.async.commit_group;" ::: "memory")
#define CP_WAIT1()  asm volatile("cp.async.wait_group 1;" ::: "memory")
#define CP_WAIT0()  asm volatile("cp.async.wait_group 0;" ::: "memory")
#define LDM4(r0, r1, r2, r3, addr) \
    asm volatile("ldmatrix.sync.aligned.m8n8.x4.shared.b16 {%0,%1,%2,%3}, [%4];" \
        : "=r"(r0), "=r"(r1), "=r"(r2), "=r"(r3) : "r"(addr))

__device__ __forceinline__ void mma_f16(float* c, uint32_t a0, uint32_t a1, uint32_t a2,
                                        uint32_t a3, uint32_t b0, uint32_t b1) {
    asm volatile(
        "mma.sync.aligned.m16n8k16.row.col.f32.f16.f16.f32 "
        "{%0,%1,%2,%3}, {%4,%5,%6,%7}, {%8,%9}, {%0,%1,%2,%3};\n"
        : "+f"(c[0]), "+f"(c[1]), "+f"(c[2]), "+f"(c[3])
        : "r"(a0), "r"(a1), "r"(a2), "r"(a3), "r"(b0), "r"(b1));
}
__device__ __forceinline__ int load_id(const void* ids, int i, int is64) {
    return is64 ? (int)((const long long*)ids)[i] : ((const int*)ids)[i];
}
__device__ __forceinline__ void ldg_x(float4 xr[4], const float* src) {
#pragma unroll
    for (int q = 0; q < 4; q++) xr[q] = __ldg((const float4*)src + q);
}
__device__ __forceinline__ void sts_x(char* dst, const float4 xr[4]) {
    uint32_t* xd = (uint32_t*)dst;
#pragma unroll
    for (int q = 0; q < 4; q++) {
        xd[2 * q]     = pack2(xr[q].x, xr[q].y);
        xd[2 * q + 1] = pack2(xr[q].z, xr[q].w);
    }
}

// ---------------- launch 1: fused hist + scan + scatter + weight transpose ----------------
__global__ void __launch_bounds__(256) k_prep(const void* __restrict__ ids, int B,
                                              const float* __restrict__ W1,
                                              const float* __restrict__ W2) {
    const int blk = blockIdx.x;
    const int t = threadIdx.x;
    if (blk < NHB) {
        __shared__ int sc[E];
        __shared__ int sbad;
        __shared__ int ticket;
        if (t < E) sc[t] = 0;
        if (t == 0) sbad = 0;
        __syncthreads();
        {   // dtype probe
            const long long* p = (const long long*)ids;
            int n = min(B / 2, 256);
            if (t < n) { long long v = p[t]; if (v < 0 || v >= E) sbad = 1; }
        }
        __syncthreads();
        const int is64 = !sbad;
        for (int i = blk * 256 + t; i < B; i += NHB * 256) {
            int e = load_id(ids, i, is64);
            if ((unsigned)e < E) atomicAdd(&sc[e], 1);
        }
        __syncthreads();
        if (t < E) d_blk[blk * E + t] = sc[t];
        __threadfence();
        if (t == 0) ticket = atomicAdd(&d_tick, 1);
        __syncthreads();
        if (ticket == NHB - 1 && t == 0) {
            int a = 0;
            for (int e = 0; e < E; e++) {
                int s = 0;
                for (int b = 0; b < NHB; b++) s += d_blk[b * E + e];
                d_offsets[e] = a; d_cursor[e] = a; a += s;
            }
            d_offsets[E] = a;
            d_tick = 0;
            __threadfence();
            d_flag = 1;
        }
        if (t == 0) { while (d_flag == 0) {} }
        __syncthreads();
        __threadfence();
        for (int i = blk * 256 + t; i < B; i += NHB * 256) {
            int e = load_id(ids, i, is64);
            if ((unsigned)e < E) {
                int p = atomicAdd(&d_cursor[e], 1);
                d_perm[p] = i;
            }
        }
    } else {
        __shared__ float ts[32][33];
        const int tx = t & 31, ty = t >> 5;
        const int tile = blk - NHB;
        const float* src;
        __half* dst;
        int k0, n0, srcLD, dstLD;
        if (tile < 336) {           // W1 [D][H] -> w1t [H][D]
            int e = tile / 48, r = tile % 48;
            k0 = (r >> 1) * 32; n0 = (r & 1) * 32;
            src = W1 + (size_t)e * D * H;  srcLD = H;
            dst = d_w1t + (size_t)e * H * D; dstLD = D;
        } else {                    // W2 [H][D] -> w2t [D][H]
            int t2 = tile - 336;
            int e = t2 / 48, r = t2 % 48;
            k0 = (r / 24) * 32; n0 = (r % 24) * 32;
            src = W2 + (size_t)e * H * D;  srcLD = D;
            dst = d_w2t + (size_t)e * D * H; dstLD = H;
        }
#pragma unroll
        for (int p = 0; p < 4; p++)
            ts[ty + 8 * p][tx] = src[(size_t)(k0 + ty + 8 * p) * srcLD + n0 + tx];
        __syncthreads();
#pragma unroll
        for (int p = 0; p < 4; p++)
            dst[(size_t)(n0 + ty + 8 * p) * dstLD + k0 + tx] =
                __float2half(ts[tx][ty + 8 * p]);
    }
}

// ---------------- smem layout (bytes) ----------------
// W1res  @ 0      : 64 * 1552          = 99328
// Xs[2]  @ 99328  : 2 * 128*144        = 36864
// Hs     @ 136192 : 128*144            = 18432
// W2ring @ 154624 : 3 * 64*144         = 27648
// b1s    @ 182272 : 256
// b2s    @ 182528 : 3072
// rowI   @ 185600 : 512
#define ROWB 144
#define W1LD 1552
#define OFF_W1 0
#define OFF_XS 99328
#define OFF_HS 136192
#define OFF_WR 154624
#define OFF_B1 182272
#define OFF_B2 182528
#define OFF_RI 185600
#define SMEM_BYTES 186112

__device__ __forceinline__ void g1_chunk(float acc[4][4], uint32_t aB, uint32_t wB) {
#pragma unroll
    for (int ks = 0; ks < 4; ks++) {
        uint32_t a0, a1, a2, a3;
        LDM4(a0, a1, a2, a3, aB + ks * 32);
#pragma unroll
        for (int jt = 0; jt < 2; jt++) {
            uint32_t r0, r1, r2, r3;
            LDM4(r0, r1, r2, r3, wB + jt * 16 * W1LD + ks * 32);
            mma_f16(acc[2 * jt],     a0, a1, a2, a3, r0, r1);
            mma_f16(acc[2 * jt + 1], a0, a1, a2, a3, r2, r3);
        }
    }
}

// ---------------- launch 2: fused persistent kernel (W1 resident, W2 ring, Hs smem) ----------------
__global__ void __launch_bounds__(512)
k_main(const float* __restrict__ x, const float* __restrict__ b1,
       const float* __restrict__ b2, float* __restrict__ out)
{
    if (blockIdx.x == 0 && blockIdx.y == 0 && threadIdx.x == 0) d_flag = 0;

    const int e = blockIdx.y, cta = blockIdx.x;
    const int seg0 = d_offsets[e], seg1 = d_offsets[e + 1];
    const int ntiles = (seg1 - seg0 + 127) >> 7;

    extern __shared__ char smc[];
    const uint32_t sb = smem_u32(smc);
    float* b1s = (float*)(smc + OFF_B1);
    float* b2s = (float*)(smc + OFF_B2);
    int* rowI = (int*)(smc + OFF_RI);

    const int tid = threadIdx.x, w = tid >> 5, lane = tid & 31;
    const int mw = w & 7, nw = w >> 3;          // 8 M-warps x 2 N-warps
    const int g = lane >> 2, tig = lane & 3;

    // ---- resident W1 (64 n-rows x 768 k halfs) via cp.async ----
    {
        const __half* W1e = d_w1t + (size_t)e * H * D;
        const int r = tid >> 3, sg = tid & 7;
        const uint32_t dst = sb + OFF_W1 + r * W1LD + sg * 192;
        const __half* src = W1e + r * D + sg * 96;
#pragma unroll
        for (int q = 0; q < 12; q++) cpa16(dst + q * 16, src + q * 8);
        CP_COMMIT();
    }
    if (tid < H) b1s[tid] = b1[e * H + tid];
    for (int i = tid; i < D; i += 512) b2s[i] = b2[e * D + i];

    const __half* W2e = d_w2t + (size_t)e * D * H;

    // fragment address cores
    const uint32_t a_core = sb + OFF_XS + (mw * 16 + (lane & 15)) * ROWB + ((lane >> 4) & 1) * 16;
    const uint32_t w1_core = sb + OFF_W1 + (nw * 32 + (lane & 7) + ((lane >> 4) & 1) * 8) * W1LD
                           + ((lane >> 3) & 1) * 16;
    const uint32_t h_core = sb + OFF_HS + (mw * 16 + (lane & 15)) * ROWB + ((lane >> 4) & 1) * 16;
    const uint32_t w2_core = (nw * 32 + (lane & 7) + ((lane >> 4) & 1) * 8) * ROWB
                           + ((lane >> 3) & 1) * 16;

    // loaders
    const int xr_ = tid >> 2, xs_ = tid & 3;                 // X: row, 16-float seg
    char* const xb0 = smc + OFF_XS + xr_ * ROWB + xs_ * 32;
    char* const xb1 = xb0 + 18432;
    const int w2r = tid >> 3, w2s = tid & 7;                 // W2: n-row, 16B seg
    const uint32_t wr_dst = sb + OFF_WR + w2r * ROWB + w2s * 16;

#pragma unroll 1
    for (int tile = cta; tile < ntiles; tile += CPE) {
        const int row0 = seg0 + tile * 128;
        const int nrows = min(128, seg1 - row0);
        __syncthreads();                 // prev tile fully done (rowI/Xs/Hs reuse)
        if (tid < 128) rowI[tid] = d_perm[row0 + min(tid, nrows - 1)];
        __syncthreads();
        const float* xg = x + (size_t)rowI[xr_] * D + xs_ * 16;

        // ---- dist-2 X prologue: c0->buf0, c1->xrO, c2->xrE ----
        float4 xrE[4], xrO[4];
        ldg_x(xrE, xg);
        sts_x(xb0, xrE);
        ldg_x(xrO, xg + 64);
        ldg_x(xrE, xg + 128);
        CP_WAIT0();                      // W1 resident (no-op after tile 0)
        __syncthreads();

        // ============ GEMM1: h = relu(X @ W1^T + b1) ============
        float acc[4][4];
#pragma unroll
        for (int nt = 0; nt < 4; nt++)
#pragma unroll
            for (int q = 0; q < 4; q++) acc[nt][q] = 0.f;

#pragma unroll 1
        for (int ii = 0; ii < 6; ii++) {
            const int i0 = 2 * ii, i1 = i0 + 1;
            sts_x(xb1, xrO);                               // c(i0+1)
            if (i0 + 3 < 12) ldg_x(xrO, xg + (i0 + 3) * 64);
            g1_chunk(acc, a_core, w1_core + i0 * 128);
            __syncthreads();
            if (i1 + 1 < 12) sts_x(xb0, xrE);              // c(i1+1)
            if (i1 + 3 < 12) ldg_x(xrE, xg + (i1 + 3) * 64);
            g1_chunk(acc, a_core + 18432, w1_core + i1 * 128);
            __syncthreads();
        }

        // ---- epilogue1: Hs = fp16(relu(acc + b1)) ----
#pragma unroll
        for (int nt = 0; nt < 4; nt++) {
            const int c = nw * 32 + nt * 8 + 2 * tig;
            float v0 = acc[nt][0] + b1s[c];
            float v1 = acc[nt][1] + b1s[c + 1];
            float v2 = acc[nt][2] + b1s[c];
            float v3 = acc[nt][3] + b1s[c + 1];
            *(uint32_t*)(smc + OFF_HS + (mw * 16 + g) * ROWB + c * 2) =
                pack2(v0 > 0.f ? v0 : 0.f, v1 > 0.f ? v1 : 0.f);
            *(uint32_t*)(smc + OFF_HS + (mw * 16 + g + 8) * ROWB + c * 2) =
                pack2(v2 > 0.f ? v2 : 0.f, v3 > 0.f ? v3 : 0.f);
        }

        // ---- W2 chunks 0,1 into ring slots 0,1 (L2-hot) ----
        cpa16(wr_dst, W2e + (size_t)w2r * H + w2s * 8);
        CP_COMMIT();                                        // W2 c0 -> slot0
        cpa16(wr_dst + 9216, W2e + (size_t)(64 + w2r) * H + w2s * 8);
        CP_COMMIT();                                        // W2 c1 -> slot1
        CP_WAIT1();                                         // slot0 ready
        __syncthreads();                                    // Hs visible + slot0

        // ---- A-fragments of h (registers, reused for all 12 N-chunks) ----
        uint32_t ha[4][4];
#pragma unroll
        for (int ks = 0; ks < 4; ks++)
            LDM4(ha[ks][0], ha[ks][1], ha[ks][2], ha[ks][3], h_core + ks * 32);

        const int rlo = mw * 16 + g, rhi = rlo + 8;
        const bool vlo = rlo < nrows, vhi = rhi < nrows;
        const float* xlo = x + (size_t)rowI[rlo] * D;
        const float* xhi = x + (size_t)rowI[rhi] * D;
        float* olo = out + (size_t)rowI[rlo] * D;
        float* ohi = out + (size_t)rowI[rhi] * D;

        // ============ GEMM2: out = x + h @ W2^T + b2 (x from L2) ============
        int rc = 2;
#pragma unroll 1
        for (int j = 0; j < 12; j++) {
            if (j + 2 < 12) {
                cpa16(wr_dst + rc * 9216, W2e + (size_t)((j + 2) * 64 + w2r) * H + w2s * 8);
                CP_COMMIT();
                rc = (rc == 2) ? 0 : rc + 1;
            }
            // epilogue-x prefetch (L2-hot: same tile read in GEMM1)
            float2 xel[4], xeh[4];
#pragma unroll
            for (int nt = 0; nt < 4; nt++) {
                const int cl = j * 64 + nw * 32 + nt * 8 + 2 * tig;
                xel[nt] = *(const float2*)(xlo + cl);
                xeh[nt] = *(const float2*)(xhi + cl);
            }
            float acc2[4][4];
#pragma unroll
            for (int nt = 0; nt < 4; nt++)
#pragma unroll
                for (int q = 0; q < 4; q++) acc2[nt][q] = 0.f;

            const int rj = j - (j / 3) * 3;   // j % 3
            const uint32_t wB = sb + OFF_WR + rj * 9216 + w2_core;
#pragma unroll
            for (int ks = 0; ks < 4; ks++) {
#pragma unroll
                for (int jt = 0; jt < 2; jt++) {
                    uint32_t r0, r1, r2, r3;
                    LDM4(r0, r1, r2, r3, wB + jt * 16 * ROWB + ks * 32);
                    mma_f16(acc2[2 * jt],     ha[ks][0], ha[ks][1], ha[ks][2], ha[ks][3], r0, r1);
                    mma_f16(acc2[2 * jt + 1], ha[ks][0], ha[ks][1], ha[ks][2], ha[ks][3], r2, r3);
                }
            }
#pragma unroll
            for (int nt = 0; nt < 4; nt++) {
                const int cl = j * 64 + nw * 32 + nt * 8 + 2 * tig;
                float2 bv = *(const float2*)(b2s + cl);
                if (vlo) {
                    float2 o = make_float2(xel[nt].x + acc2[nt][0] + bv.x,
                                           xel[nt].y + acc2[nt][1] + bv.y);
                    *(float2*)(olo + cl) = o;
                }
                if (vhi) {
                    float2 o = make_float2(xeh[nt].x + acc2[nt][2] + bv.x,
                                           xeh[nt].y + acc2[nt][3] + bv.y);
                    *(float2*)(ohi + cl) = o;
                }
            }
            if (j < 10) CP_WAIT1(); else CP_WAIT0();
            __syncthreads();
        }
    }
}

extern "C" void kernel_launch(void* const* d_in, const int* in_sizes, int n_in,
                              void* d_out, int out_size)
{
    const float* x   = (const float*)d_in[0];
    const void*  ids = d_in[1];
    const float* W1  = (const float*)d_in[2];
    const float* b1  = (const float*)d_in[3];
    const float* W2  = (const float*)d_in[4];
    const float* b2  = (const float*)d_in[5];
    float*       out = (float*)d_out;

    const int B = in_sizes[1];

    k_prep<<<NHB + 672, 256>>>(ids, B, W1, W2);

    cudaFuncSetAttribute(k_main, cudaFuncAttributeMaxDynamicSharedMemorySize, SMEM_BYTES);
    dim3 grid(CPE, E);
    k_main<<<grid, 512, SMEM_BYTES>>>(x, b1, b2, out);
}